// round 13
// baseline (speedup 1.0000x reference)
#include <cuda_runtime.h>
#include <cstdint>

#define NN   50000
#define EE   800000
#define FEAT 128
#define HID  128
#define EPSL 1e-5f

#define ASTR 132          // MMA A-tile stride (floats)
#define BSTR 136          // MMA weight-tile stride (floats)

// ---------------- scratch (device globals) -----------------------------------
__device__ float g_A[NN * FEAT];      // x @ Wa   (e_w1 rows   0..127)
__device__ float g_B[NN * FEAT];      // x @ Wb   (e_w1 rows 128..255)
__device__ float g_aggm[NN * HID];    // segment-sum of m_ij
__device__ int   g_src[EE];
__device__ int   g_dst[EE];

__device__ __forceinline__ float silu_f(float v) {
    return __fdividef(v, 1.0f + __expf(-v));
}
__device__ __forceinline__ uint32_t f2tf32(float f) {
    uint32_t r; asm("cvt.rna.tf32.f32 %0, %1;" : "=r"(r) : "f"(f)); return r;
}
// column permutation within each 32-block so a thread's 4 B-frag values are contiguous
__device__ __forceinline__ int permn(int n) {
    return (n & ~31) + ((n & 7) << 2) + ((n >> 3) & 3);
}
__device__ __forceinline__ void mma8(float* d, const uint32_t* a, const uint32_t* b) {
    asm volatile("mma.sync.aligned.m16n8k8.row.col.f32.tf32.tf32.f32 "
                 "{%0,%1,%2,%3}, {%4,%5,%6,%7}, {%8,%9}, {%0,%1,%2,%3};"
                 : "+f"(d[0]), "+f"(d[1]), "+f"(d[2]), "+f"(d[3])
                 : "r"(a[0]), "r"(a[1]), "r"(a[2]), "r"(a[3]), "r"(b[0]), "r"(b[1]));
}

// per-warp tf32 GEMM: C[16x32] += A[16x128] * B[128x32]; B is n-permuted
__device__ __forceinline__ void warp_gemm1(const uint32_t* __restrict__ Au,
                                           const uint32_t* __restrict__ Bu,
                                           float c[4][4],
                                           int mbase, int nbase, int g, int t)
{
#pragma unroll 1
    for (int ks = 0; ks < 16; ks++) {
        int kk = ks * 8;
        uint32_t af[4];
        {
            const uint32_t* p = Au + (mbase + g) * ASTR + kk + t;
            af[0] = p[0];
            af[1] = p[8 * ASTR];
            af[2] = p[4];
            af[3] = p[8 * ASTR + 4];
        }
        const uint32_t* pb = Bu + (kk + t) * BSTR + nbase + 4 * g;
        uint4 b0 = *(const uint4*)pb;
        uint4 b1 = *(const uint4*)(pb + 4 * BSTR);
        uint32_t bf[4][2] = {{b0.x, b1.x}, {b0.y, b1.y}, {b0.z, b1.z}, {b0.w, b1.w}};
#pragma unroll
        for (int nt = 0; nt < 4; nt++)
            mma8(c[nt], af, bf[nt]);
    }
}

// per-warp tf32 GEMM (512-thr kernels): C[32x32] += A[32x128] * B[128x32]; B n-permuted
__device__ __forceinline__ void warp_gemm2(const uint32_t* __restrict__ Au,
                                           const uint32_t* __restrict__ Bu,
                                           float c[2][4][4],
                                           int mbase, int nbase, int g, int t)
{
#pragma unroll 1
    for (int ks = 0; ks < 16; ks++) {
        int kk = ks * 8;
        uint32_t af[2][4];
#pragma unroll
        for (int mt = 0; mt < 2; mt++) {
            const uint32_t* p = Au + (mbase + mt * 16 + g) * ASTR + kk + t;
            af[mt][0] = p[0];
            af[mt][1] = p[8 * ASTR];
            af[mt][2] = p[4];
            af[mt][3] = p[8 * ASTR + 4];
        }
        const uint32_t* pb = Bu + (kk + t) * BSTR + nbase + 4 * g;
        uint4 b0 = *(const uint4*)pb;
        uint4 b1 = *(const uint4*)(pb + 4 * BSTR);
        uint32_t bf[4][2] = {{b0.x, b1.x}, {b0.y, b1.y}, {b0.z, b1.z}, {b0.w, b1.w}};
#pragma unroll
        for (int mt = 0; mt < 2; mt++)
#pragma unroll
            for (int nt = 0; nt < 4; nt++)
                mma8(c[mt][nt], af[mt], bf[nt]);
    }
}

// ---------------- K-1: normalize edge_index dtype ----------------------------
__global__ void conv_idx_kernel(const void* __restrict__ ei_raw)
{
    const long long* e64 = (const long long*)ei_raw;
    const int*       e32 = (const int*)ei_raw;
    bool is64 = true;
#pragma unroll
    for (int j = 0; j < 8; j++) {
        long long v = e64[j];
        if (v < 0 || v >= NN) is64 = false;
    }
    int i = blockIdx.x * blockDim.x + threadIdx.x;
    int stride = gridDim.x * blockDim.x;
    if (is64) {
        for (int e = i; e < EE; e += stride) {
            g_src[e] = (int)e64[e];
            g_dst[e] = (int)e64[EE + e];
        }
    } else {
        for (int e = i; e < EE; e += stride) {
            g_src[e] = e32[e];
            g_dst[e] = e32[EE + e];
        }
    }
}

// ---------------- K0: zero agg_m, pos_out = pos ------------------------------
__global__ void init_kernel(const float* __restrict__ pos, float* __restrict__ out_pos)
{
    int i = blockIdx.x * blockDim.x + threadIdx.x;
    int stride = gridDim.x * blockDim.x;
    for (int j = i; j < NN * HID; j += stride) g_aggm[j] = 0.0f;
    for (int j = i; j < NN * 3;   j += stride) out_pos[j] = pos[j];
}

// ---------------- K1: A = x@Wa, B = x@Wb (tf32 MMA, 512 thr) ------------------
#define PB_SMEM (51712 * 4)
__global__ __launch_bounds__(512, 1)
void preab_kernel(const float* __restrict__ x, const float* __restrict__ e_w1)
{
    extern __shared__ float sm[];
    float* As  = sm;
    float* B1s = sm + 16896;
    float* B2s = sm + 34304;
    const uint32_t* Au  = (const uint32_t*)As;
    const uint32_t* B1u = (const uint32_t*)B1s;
    const uint32_t* B2u = (const uint32_t*)B2s;

    int tid = threadIdx.x, warp = tid >> 5, lane = tid & 31;
    int g = lane >> 2, t = lane & 3;
    int wm = warp >> 2, wn = warp & 3;
    int mbase = wm * 32, nbase = wn * 32;
    int n0 = blockIdx.x * 128;

    for (int idx = tid; idx < 16384; idx += 512) {
        int row = idx >> 7, k = idx & 127;
        float v = (n0 + row < NN) ? x[(size_t)(n0 + row) * 128 + k] : 0.f;
        As[row * ASTR + k]  = __uint_as_float(f2tf32(v));
        int kp = permn(k);
        B1s[row * BSTR + kp] = __uint_as_float(f2tf32(e_w1[row * 128 + k]));
        B2s[row * BSTR + kp] = __uint_as_float(f2tf32(e_w1[(128 + row) * 128 + k]));
    }
    __syncthreads();

    float c[2][4][4];
#pragma unroll
    for (int mt = 0; mt < 2; mt++)
#pragma unroll
        for (int nt = 0; nt < 4; nt++)
#pragma unroll
            for (int j = 0; j < 4; j++) c[mt][nt][j] = 0.f;
    warp_gemm2(Au, B1u, c, mbase, nbase, g, t);
#pragma unroll
    for (int mt = 0; mt < 2; mt++) {
        int r0 = mbase + mt * 16 + g, r1 = r0 + 8;
#pragma unroll
        for (int nt = 0; nt < 4; nt++) {
            int c0 = nbase + nt * 8 + 2 * t;
            if (n0 + r0 < NN)
                *(float2*)(g_A + (size_t)(n0 + r0) * 128 + c0) = make_float2(c[mt][nt][0], c[mt][nt][1]);
            if (n0 + r1 < NN)
                *(float2*)(g_A + (size_t)(n0 + r1) * 128 + c0) = make_float2(c[mt][nt][2], c[mt][nt][3]);
        }
    }

#pragma unroll
    for (int mt = 0; mt < 2; mt++)
#pragma unroll
        for (int nt = 0; nt < 4; nt++)
#pragma unroll
            for (int j = 0; j < 4; j++) c[mt][nt][j] = 0.f;
    warp_gemm2(Au, B2u, c, mbase, nbase, g, t);
#pragma unroll
    for (int mt = 0; mt < 2; mt++) {
        int r0 = mbase + mt * 16 + g, r1 = r0 + 8;
#pragma unroll
        for (int nt = 0; nt < 4; nt++) {
            int c0 = nbase + nt * 8 + 2 * t;
            if (n0 + r0 < NN)
                *(float2*)(g_B + (size_t)(n0 + r0) * 128 + c0) = make_float2(c[mt][nt][0], c[mt][nt][1]);
            if (n0 + r1 < NN)
                *(float2*)(g_B + (size_t)(n0 + r1) * 128 + c0) = make_float2(c[mt][nt][2], c[mt][nt][3]);
        }
    }
}

// ---------------- K2: persistent edge kernel ----------------------------------
// Two independent 512-thread groups; interleaved epilogue constants.
#define EO_A    0                       // 2 groups x 64 x ASTR = 16896
#define EO_B1   16896
#define EO_B2   34304
#define EO_SV   51712                   // shared constants (1408 floats)
#define EO_GRP  53120                   // per-group scratch, 1408 floats each
// shared const indices (relative to sv)
#define SV_WC0  0
#define SV_WC1  128
#define SV_WD   256
#define SV_B1   384
#define SV_I1   512    // interleaved (u1, vb1) pairs, 256 floats
#define SV_IG   768    // interleaved (g2, be2) pairs, 256 floats
#define SV_I2   1024   // interleaved (u2, vb2) pairs, 256 floats
#define SV_CW2  1280   // 128 floats
// per-group indices (relative to gsv)
#define GV_RELX 0
#define GV_RELY 64
#define GV_RELZ 128
#define GV_R2   192
#define GV_EA0  256
#define GV_EA1  320
#define GV_MU1  384
#define GV_RS1  448
#define GV_SUM  512    // [64][4]
#define GV_SQ   768    // [64][4]
#define GV_SUM2 1024   // [64][4]
#define GV_IDX  1280   // ints: 64 dst, 64 src
#define GRP_FLOATS 1408
#define EDGE_SMEM ((EO_GRP + 2 * GRP_FLOATS) * 4)   // 223744 bytes

#define BARG(id) asm volatile("bar.sync %0, 512;" :: "r"(id) : "memory")

__global__ __launch_bounds__(1024, 1)
void edge_kernel(const float* __restrict__ pos,
                 const float* __restrict__ ea,
                 const float* __restrict__ e_w1, const float* __restrict__ e_b1,
                 const float* __restrict__ e_g1, const float* __restrict__ e_be1,
                 const float* __restrict__ e_w2, const float* __restrict__ e_b2,
                 const float* __restrict__ e_g2, const float* __restrict__ e_be2,
                 const float* __restrict__ c_w1, const float* __restrict__ c_b1,
                 const float* __restrict__ c_w2, const float* __restrict__ c_b2,
                 float* __restrict__ out_pos)
{
    extern __shared__ float sm[];
    float* B1s = sm + EO_B1;
    float* B2s = sm + EO_B2;
    float* sv  = sm + EO_SV;
    const uint32_t* B1u = (const uint32_t*)B1s;
    const uint32_t* B2u = (const uint32_t*)B2s;

    int tid = threadIdx.x, warp = tid >> 5, lane = tid & 31;
    int gid = warp >> 4;
    int wig = warp & 15;
    int gtid = tid & 511;
    int bar = gid + 1;
    int g = lane >> 2, t = lane & 3;
    int wm = wig >> 2, wn = wig & 3;
    int mbase = wm * 16, nbase = wn * 32;

    float* As  = sm + EO_A + gid * (64 * ASTR);
    float* gsv = sm + EO_GRP + gid * GRP_FLOATS;
    int*   gdst = (int*)(gsv + GV_IDX);
    int*   gsrc = gdst + 64;
    const uint32_t* Au = (const uint32_t*)As;

    // ---- stage LN-folded weights (tf32, n-permuted) + shared constants ----
    for (int idx = tid; idx < 16384; idx += 1024) {
        int k = idx >> 7, n = idx & 127;
        int np = permn(n);
        B1s[k * BSTR + np] = __uint_as_float(f2tf32(e_g1[k] * e_w2[k * 128 + n]));
        B2s[k * BSTR + np] = __uint_as_float(f2tf32(e_g2[k] * c_w1[k * 128 + n]));
    }
    if (tid < 128) {
        sv[SV_WC0 + tid] = e_w1[256 * 128 + tid];
        sv[SV_WC1 + tid] = e_w1[257 * 128 + tid];
        sv[SV_WD  + tid] = e_w1[258 * 128 + tid];
        sv[SV_B1  + tid] = e_b1[tid];
        sv[SV_IG  + 2 * tid]     = e_g2[tid];
        sv[SV_IG  + 2 * tid + 1] = e_be2[tid];
        sv[SV_CW2 + tid] = c_w2[tid];
    }
    if (tid < 512) {
        int quad = tid >> 7, n = tid & 127;
        float acc = 0.f;
        if (quad == 0) {
            for (int k = 0; k < 128; k++) acc += e_g1[k] * e_w2[k * 128 + n];
            sv[SV_I1 + 2 * n] = acc;
        } else if (quad == 1) {
            for (int k = 0; k < 128; k++) acc += e_be1[k] * e_w2[k * 128 + n];
            sv[SV_I1 + 2 * n + 1] = acc + e_b2[n];
        } else if (quad == 2) {
            for (int k = 0; k < 128; k++) acc += e_g2[k] * c_w1[k * 128 + n];
            sv[SV_I2 + 2 * n] = acc;
        } else {
            for (int k = 0; k < 128; k++) acc += e_be2[k] * c_w1[k * 128 + n];
            sv[SV_I2 + 2 * n + 1] = acc + c_b1[n];
        }
    }
    float cb2 = c_b2[0];
    __syncthreads();

    int k4 = lane * 4;
    bool first = true;

    const int ntiles = EE / 64;
    for (int tile = blockIdx.x * 2 + gid; tile < ntiles; tile += 2 * gridDim.x) {
        int e0 = tile * 64;
        // ---- phase A (gtid<64): prev-tile pos atomics + stage edge meta ----
        if (gtid < 64) {
            if (!first) {
                float coef = gsv[GV_SUM2 + gtid * 4] + gsv[GV_SUM2 + gtid * 4 + 1]
                           + gsv[GV_SUM2 + gtid * 4 + 2] + gsv[GV_SUM2 + gtid * 4 + 3] + cb2;
                int dip = gdst[gtid];
                atomicAdd(&out_pos[dip * 3 + 0], gsv[GV_RELX + gtid] * coef);
                atomicAdd(&out_pos[dip * 3 + 1], gsv[GV_RELY + gtid] * coef);
                atomicAdd(&out_pos[dip * 3 + 2], gsv[GV_RELZ + gtid] * coef);
            }
            int e = e0 + gtid;
            int si = g_src[e], di = g_dst[e];
            float rx = pos[di * 3 + 0] - pos[si * 3 + 0];
            float ry = pos[di * 3 + 1] - pos[si * 3 + 1];
            float rz = pos[di * 3 + 2] - pos[si * 3 + 2];
            gsrc[gtid] = si; gdst[gtid] = di;
            gsv[GV_RELX + gtid] = rx; gsv[GV_RELY + gtid] = ry; gsv[GV_RELZ + gtid] = rz;
            gsv[GV_R2 + gtid]  = rx * rx + ry * ry + rz * rz;
            gsv[GV_EA0 + gtid] = ea[2 * e];
            gsv[GV_EA1 + gtid] = ea[2 * e + 1];
        }
        first = false;
        BARG(bar);

        // ---- layer-1: gather + SiLU -> As (raw h, tf32); row stats ----
        {
            float4 wc0 = *(const float4*)(sv + SV_WC0 + k4);
            float4 wc1 = *(const float4*)(sv + SV_WC1 + k4);
            float4 wdv = *(const float4*)(sv + SV_WD  + k4);
            float4 b1v = *(const float4*)(sv + SV_B1  + k4);
#pragma unroll 2
            for (int r = 0; r < 4; r++) {
                int row = wig * 4 + r;
                int si = gsrc[row], di = gdst[row];
                float4 a = *(const float4*)(g_A + (size_t)si * 128 + k4);
                float4 b = *(const float4*)(g_B + (size_t)di * 128 + k4);
                float e0v = gsv[GV_EA0 + row], e1v = gsv[GV_EA1 + row], r2v = gsv[GV_R2 + row];
                float4 o;
                o.x = silu_f(a.x + b.x + e0v * wc0.x + e1v * wc1.x + r2v * wdv.x + b1v.x);
                o.y = silu_f(a.y + b.y + e0v * wc0.y + e1v * wc1.y + r2v * wdv.y + b1v.y);
                o.z = silu_f(a.z + b.z + e0v * wc0.z + e1v * wc1.z + r2v * wdv.z + b1v.z);
                o.w = silu_f(a.w + b.w + e0v * wc0.w + e1v * wc1.w + r2v * wdv.w + b1v.w);
                float s = o.x + o.y + o.z + o.w;
                float q = o.x * o.x + o.y * o.y + o.z * o.z + o.w * o.w;
#pragma unroll
                for (int off = 16; off > 0; off >>= 1) {
                    s += __shfl_xor_sync(0xffffffffu, s, off);
                    q += __shfl_xor_sync(0xffffffffu, q, off);
                }
                uint4 tv;
                tv.x = f2tf32(o.x); tv.y = f2tf32(o.y);
                tv.z = f2tf32(o.z); tv.w = f2tf32(o.w);
                *(uint4*)(As + row * ASTR + k4) = tv;
                if (lane == 0) {
                    float mu = s * (1.0f / 128.0f);
                    gsv[GV_MU1 + row] = mu;
                    gsv[GV_RS1 + row] = rsqrtf(q * (1.0f / 128.0f) - mu * mu + EPSL);
                }
            }
        }
        BARG(bar);

        // ---- GEMM1: h @ (g1 ∘ e_w2) ----
        float c[4][4];
#pragma unroll
        for (int nt = 0; nt < 4; nt++)
#pragma unroll
            for (int j = 0; j < 4; j++) c[nt][j] = 0.f;
        warp_gemm1(Au, B1u, c, mbase, nbase, g, t);
        BARG(bar);

        // ---- ep1: y = rs1*(d - mu1*u1) + vb1 ; z = silu(y) -> As + partials ----
        {
            int r0 = mbase + g, r1 = r0 + 8;
            float rsA = gsv[GV_RS1 + r0], bA = rsA * gsv[GV_MU1 + r0];
            float rsB = gsv[GV_RS1 + r1], bB = rsB * gsv[GV_MU1 + r1];
            float s0 = 0.f, q0 = 0.f, s1 = 0.f, q1 = 0.f;
#pragma unroll
            for (int nt = 0; nt < 4; nt++) {
                int c0 = nbase + nt * 8 + 2 * t;
                float4 P = *(const float4*)(sv + SV_I1 + 2 * c0);   // u1a, vba, u1b, vbb
                float z0 = silu_f(rsA * c[nt][0] - bA * P.x + P.y);
                float z1 = silu_f(rsA * c[nt][1] - bA * P.z + P.w);
                float z2 = silu_f(rsB * c[nt][2] - bB * P.x + P.y);
                float z3 = silu_f(rsB * c[nt][3] - bB * P.z + P.w);
                c[nt][0] = z0; c[nt][1] = z1; c[nt][2] = z2; c[nt][3] = z3;
                uint2 p0; p0.x = f2tf32(z0); p0.y = f2tf32(z1);
                uint2 p1; p1.x = f2tf32(z2); p1.y = f2tf32(z3);
                *(uint2*)(As + r0 * ASTR + c0) = p0;
                *(uint2*)(As + r1 * ASTR + c0) = p1;
                s0 += z0 + z1; q0 += z0 * z0 + z1 * z1;
                s1 += z2 + z3; q1 += z2 * z2 + z3 * z3;
            }
#pragma unroll
            for (int off = 1; off <= 2; off <<= 1) {
                s0 += __shfl_xor_sync(0xffffffffu, s0, off);
                s1 += __shfl_xor_sync(0xffffffffu, s1, off);
                q0 += __shfl_xor_sync(0xffffffffu, q0, off);
                q1 += __shfl_xor_sync(0xffffffffu, q1, off);
            }
            if (t == 0) {
                gsv[GV_SUM + r0 * 4 + wn] = s0;
                gsv[GV_SQ  + r0 * 4 + wn] = q0;
                gsv[GV_SUM + r1 * 4 + wn] = s1;
                gsv[GV_SQ  + r1 * 4 + wn] = q1;
            }
        }
        BARG(bar);

        // ---- phase B: local LN2 stats, aggm atomics, GEMM2, ep2 partials ----
        {
            int r0 = mbase + g, r1 = r0 + 8;
            float s0 = gsv[GV_SUM + r0 * 4] + gsv[GV_SUM + r0 * 4 + 1]
                     + gsv[GV_SUM + r0 * 4 + 2] + gsv[GV_SUM + r0 * 4 + 3];
            float q0 = gsv[GV_SQ + r0 * 4] + gsv[GV_SQ + r0 * 4 + 1]
                     + gsv[GV_SQ + r0 * 4 + 2] + gsv[GV_SQ + r0 * 4 + 3];
            float s1 = gsv[GV_SUM + r1 * 4] + gsv[GV_SUM + r1 * 4 + 1]
                     + gsv[GV_SUM + r1 * 4 + 2] + gsv[GV_SUM + r1 * 4 + 3];
            float q1 = gsv[GV_SQ + r1 * 4] + gsv[GV_SQ + r1 * 4 + 1]
                     + gsv[GV_SQ + r1 * 4 + 2] + gsv[GV_SQ + r1 * 4 + 3];
            float mu0 = s0 * (1.0f / 128.0f);
            float rs0 = rsqrtf(q0 * (1.0f / 128.0f) - mu0 * mu0 + EPSL);
            float mu1 = s1 * (1.0f / 128.0f);
            float rs1 = rsqrtf(q1 * (1.0f / 128.0f) - mu1 * mu1 + EPSL);

            int d0 = gdst[r0], d1 = gdst[r1];
#pragma unroll
            for (int nt = 0; nt < 4; nt++) {
                int c0 = nbase + nt * 8 + 2 * t;
                float4 G = *(const float4*)(sv + SV_IG + 2 * c0);   // g2a, bea, g2b, beb
                float m0 = (c[nt][0] - mu0) * rs0 * G.x + G.y;
                float m1 = (c[nt][1] - mu0) * rs0 * G.z + G.w;
                float m2 = (c[nt][2] - mu1) * rs1 * G.x + G.y;
                float m3 = (c[nt][3] - mu1) * rs1 * G.z + G.w;
                asm volatile("red.global.add.v2.f32 [%0], {%1, %2};"
                             :: "l"(g_aggm + (size_t)d0 * 128 + c0), "f"(m0), "f"(m1) : "memory");
                asm volatile("red.global.add.v2.f32 [%0], {%1, %2};"
                             :: "l"(g_aggm + (size_t)d1 * 128 + c0), "f"(m2), "f"(m3) : "memory");
            }

            // GEMM2: z @ (g2 ∘ c_w1)
#pragma unroll
            for (int nt = 0; nt < 4; nt++)
#pragma unroll
                for (int j = 0; j < 4; j++) c[nt][j] = 0.f;
            warp_gemm1(Au, B2u, c, mbase, nbase, g, t);

            // ep2: val = rs*(d - mu*u2) + vb2 ; coef partials -> SUM2
            float b0 = rs0 * mu0, b1 = rs1 * mu1;
            float p0 = 0.f, p1 = 0.f;
#pragma unroll
            for (int nt = 0; nt < 4; nt++) {
                int c0 = nbase + nt * 8 + 2 * t;
                float4 Q = *(const float4*)(sv + SV_I2 + 2 * c0);   // u2a, vba, u2b, vbb
                float2 W = *(const float2*)(sv + SV_CW2 + c0);
                p0 += silu_f(rs0 * c[nt][0] - b0 * Q.x + Q.y) * W.x
                    + silu_f(rs0 * c[nt][1] - b0 * Q.z + Q.w) * W.y;
                p1 += silu_f(rs1 * c[nt][2] - b1 * Q.x + Q.y) * W.x
                    + silu_f(rs1 * c[nt][3] - b1 * Q.z + Q.w) * W.y;
            }
#pragma unroll
            for (int off = 1; off <= 2; off <<= 1) {
                p0 += __shfl_xor_sync(0xffffffffu, p0, off);
                p1 += __shfl_xor_sync(0xffffffffu, p1, off);
            }
            if (t == 0) {
                gsv[GV_SUM2 + r0 * 4 + wn] = p0;
                gsv[GV_SUM2 + r1 * 4 + wn] = p1;
            }
        }
        BARG(bar);
    }

    // ---- final tile's pos atomics (per group) ----
    if (!first && gtid < 64) {
        float coef = gsv[GV_SUM2 + gtid * 4] + gsv[GV_SUM2 + gtid * 4 + 1]
                   + gsv[GV_SUM2 + gtid * 4 + 2] + gsv[GV_SUM2 + gtid * 4 + 3] + cb2;
        int di = gdst[gtid];
        atomicAdd(&out_pos[di * 3 + 0], gsv[GV_RELX + gtid] * coef);
        atomicAdd(&out_pos[di * 3 + 1], gsv[GV_RELY + gtid] * coef);
        atomicAdd(&out_pos[di * 3 + 2], gsv[GV_RELZ + gtid] * coef);
    }
}

// ---------------- K3: node MLP + residual (tf32 MMA, 512 thr) ----------------
#define NV_B1   0
#define NV_I    128    // interleaved (u, vb) pairs, 256 floats
#define NV_MU   384
#define NV_RS   512
#define NV_SUM  640    // [128][4]
#define NV_SQ   1152   // [128][4]
#define NV_FLOATS 1664
#define ND_SMEM ((34304 + NV_FLOATS) * 4)
__global__ __launch_bounds__(512, 1)
void node_kernel(const float* __restrict__ x,
                 const float* __restrict__ n_w1, const float* __restrict__ n_b1,
                 const float* __restrict__ n_g1, const float* __restrict__ n_be1,
                 const float* __restrict__ n_w2, const float* __restrict__ n_b2,
                 float* __restrict__ out_x)
{
    extern __shared__ float sm[];
    float* As = sm;
    float* Bs = sm + 16896;
    float* sv = sm + 34304;
    const uint32_t* Au = (const uint32_t*)As;
    const uint32_t* Bu = (const uint32_t*)Bs;

    int tid = threadIdx.x, warp = tid >> 5, lane = tid & 31;
    int g = lane >> 2, t = lane & 3;
    int wm = warp >> 2, wn = warp & 3;
    int mbase = wm * 32, nbase = wn * 32;
    int n0 = blockIdx.x * 128;

    if (tid < 128) sv[NV_B1 + tid] = n_b1[tid];
    if (tid >= 128 && tid < 384) {
        int half = (tid - 128) >> 7, n = tid & 127;
        float acc = 0.f;
        if (half == 0) {
            for (int k = 0; k < 128; k++) acc += n_g1[k] * n_w2[k * 128 + n];
            sv[NV_I + 2 * n] = acc;
        } else {
            for (int k = 0; k < 128; k++) acc += n_be1[k] * n_w2[k * 128 + n];
            sv[NV_I + 2 * n + 1] = acc + n_b2[n];
        }
    }

    // phase 1: x @ W1a
    for (int idx = tid; idx < 16384; idx += 512) {
        int row = idx >> 7, k = idx & 127;
        float v = (n0 + row < NN) ? x[(size_t)(n0 + row) * 128 + k] : 0.f;
        As[row * ASTR + k] = __uint_as_float(f2tf32(v));
        Bs[row * BSTR + permn(k)] = __uint_as_float(f2tf32(n_w1[row * 128 + k]));
    }
    __syncthreads();

    float c[2][4][4];
#pragma unroll
    for (int mt = 0; mt < 2; mt++)
#pragma unroll
        for (int nt = 0; nt < 4; nt++)
#pragma unroll
            for (int j = 0; j < 4; j++) c[mt][nt][j] = 0.f;
    warp_gemm2(Au, Bu, c, mbase, nbase, g, t);
    __syncthreads();

    // phase 2: + aggm @ W1b
    for (int idx = tid; idx < 16384; idx += 512) {
        int row = idx >> 7, k = idx & 127;
        float v = (n0 + row < NN) ? g_aggm[(size_t)(n0 + row) * 128 + k] : 0.f;
        As[row * ASTR + k] = __uint_as_float(f2tf32(v));
        Bs[row * BSTR + permn(k)] = __uint_as_float(f2tf32(n_w1[(128 + row) * 128 + k]));
    }
    __syncthreads();
    warp_gemm2(Au, Bu, c, mbase, nbase, g, t);
    __syncthreads();

    // ep1: z = silu(acc + b1) -> As (tf32) + row stats
#pragma unroll
    for (int mt = 0; mt < 2; mt++) {
        int r0 = mbase + mt * 16 + g, r1 = r0 + 8;
        float s0 = 0.f, q0 = 0.f, s1 = 0.f, q1 = 0.f;
#pragma unroll
        for (int nt = 0; nt < 4; nt++) {
            int c0 = nbase + nt * 8 + 2 * t;
            float ba = sv[NV_B1 + c0], bb = sv[NV_B1 + c0 + 1];
            float z0 = silu_f(c[mt][nt][0] + ba);
            float z1 = silu_f(c[mt][nt][1] + bb);
            float z2 = silu_f(c[mt][nt][2] + ba);
            float z3 = silu_f(c[mt][nt][3] + bb);
            uint2 p0; p0.x = f2tf32(z0); p0.y = f2tf32(z1);
            uint2 p1; p1.x = f2tf32(z2); p1.y = f2tf32(z3);
            *(uint2*)(As + r0 * ASTR + c0) = p0;
            *(uint2*)(As + r1 * ASTR + c0) = p1;
            s0 += z0 + z1; q0 += z0 * z0 + z1 * z1;
            s1 += z2 + z3; q1 += z2 * z2 + z3 * z3;
        }
#pragma unroll
        for (int off = 1; off <= 2; off <<= 1) {
            s0 += __shfl_xor_sync(0xffffffffu, s0, off);
            s1 += __shfl_xor_sync(0xffffffffu, s1, off);
            q0 += __shfl_xor_sync(0xffffffffu, q0, off);
            q1 += __shfl_xor_sync(0xffffffffu, q1, off);
        }
        if (t == 0) {
            sv[NV_SUM + r0 * 4 + wn] = s0;
            sv[NV_SQ  + r0 * 4 + wn] = q0;
            sv[NV_SUM + r1 * 4 + wn] = s1;
            sv[NV_SQ  + r1 * 4 + wn] = q1;
        }
    }
    __syncthreads();
    if (tid < 128) {
        float s = sv[NV_SUM + tid * 4] + sv[NV_SUM + tid * 4 + 1]
                + sv[NV_SUM + tid * 4 + 2] + sv[NV_SUM + tid * 4 + 3];
        float q = sv[NV_SQ + tid * 4] + sv[NV_SQ + tid * 4 + 1]
                + sv[NV_SQ + tid * 4 + 2] + sv[NV_SQ + tid * 4 + 3];
        float mu = s * (1.0f / 128.0f);
        sv[NV_MU + tid] = mu;
        sv[NV_RS + tid] = rsqrtf(q * (1.0f / 128.0f) - mu * mu + EPSL);
    }
    // stage (g1 ∘ W2) into Bs (n-permuted)
    for (int idx = tid; idx < 16384; idx += 512) {
        int k = idx >> 7, n = idx & 127;
        Bs[k * BSTR + permn(n)] = __uint_as_float(f2tf32(n_g1[k] * n_w2[k * 128 + n]));
    }
    __syncthreads();

    // GEMM2: z @ (g1 ∘ W2)
#pragma unroll
    for (int mt = 0; mt < 2; mt++)
#pragma unroll
        for (int nt = 0; nt < 4; nt++)
#pragma unroll
            for (int j = 0; j < 4; j++) c[mt][nt][j] = 0.f;
    warp_gemm2(Au, Bu, c, mbase, nbase, g, t);

    // ep2: out = x + rs*d - rs*mu*u + vb
#pragma unroll
    for (int mt = 0; mt < 2; mt++) {
        int r0 = mbase + mt * 16 + g, r1 = r0 + 8;
        float rs0 = sv[NV_RS + r0], b0 = rs0 * sv[NV_MU + r0];
        float rs1 = sv[NV_RS + r1], b1 = rs1 * sv[NV_MU + r1];
#pragma unroll
        for (int nt = 0; nt < 4; nt++) {
            int c0 = nbase + nt * 8 + 2 * t;
            float4 Q = *(const float4*)(sv + NV_I + 2 * c0);   // ua, va, ub, vb
            if (n0 + r0 < NN) {
                float2 xv = *(const float2*)(x + (size_t)(n0 + r0) * 128 + c0);
                *(float2*)(out_x + (size_t)(n0 + r0) * 128 + c0) =
                    make_float2(xv.x + rs0 * c[mt][nt][0] - b0 * Q.x + Q.y,
                                xv.y + rs0 * c[mt][nt][1] - b0 * Q.z + Q.w);
            }
            if (n0 + r1 < NN) {
                float2 xv = *(const float2*)(x + (size_t)(n0 + r1) * 128 + c0);
                *(float2*)(out_x + (size_t)(n0 + r1) * 128 + c0) =
                    make_float2(xv.x + rs1 * c[mt][nt][2] - b1 * Q.x + Q.y,
                                xv.y + rs1 * c[mt][nt][3] - b1 * Q.z + Q.w);
            }
        }
    }
}

// ---------------- launch ------------------------------------------------------
extern "C" void kernel_launch(void* const* d_in, const int* in_sizes, int n_in,
                              void* d_out, int out_size)
{
    const float*     x     = (const float*)d_in[0];
    const float*     pos   = (const float*)d_in[1];
    const void*      ei    = d_in[2];
    const float*     ea    = (const float*)d_in[3];
    const float*     e_w1  = (const float*)d_in[4];
    const float*     e_b1  = (const float*)d_in[5];
    const float*     e_g1  = (const float*)d_in[6];
    const float*     e_be1 = (const float*)d_in[7];
    const float*     e_w2  = (const float*)d_in[8];
    const float*     e_b2  = (const float*)d_in[9];
    const float*     e_g2  = (const float*)d_in[10];
    const float*     e_be2 = (const float*)d_in[11];
    const float*     n_w1  = (const float*)d_in[12];
    const float*     n_b1  = (const float*)d_in[13];
    const float*     n_g1  = (const float*)d_in[14];
    const float*     n_be1 = (const float*)d_in[15];
    const float*     n_w2  = (const float*)d_in[16];
    const float*     n_b2  = (const float*)d_in[17];
    const float*     c_w1  = (const float*)d_in[18];
    const float*     c_b1  = (const float*)d_in[19];
    const float*     c_w2  = (const float*)d_in[20];
    const float*     c_b2  = (const float*)d_in[21];

    float* out_x   = (float*)d_out;
    float* out_pos = (float*)d_out + (size_t)NN * FEAT;

    cudaFuncSetAttribute(preab_kernel, cudaFuncAttributeMaxDynamicSharedMemorySize, PB_SMEM);
    cudaFuncSetAttribute(edge_kernel,  cudaFuncAttributeMaxDynamicSharedMemorySize, EDGE_SMEM);
    cudaFuncSetAttribute(node_kernel,  cudaFuncAttributeMaxDynamicSharedMemorySize, ND_SMEM);

    conv_idx_kernel<<<256, 256>>>(ei);
    init_kernel<<<256, 256>>>(pos, out_pos);
    preab_kernel<<<(NN + 127) / 128, 512, PB_SMEM>>>(x, e_w1);
    edge_kernel<<<148, 1024, EDGE_SMEM>>>(pos, ea,
                                          e_w1, e_b1, e_g1, e_be1,
                                          e_w2, e_b2, e_g2, e_be2,
                                          c_w1, c_b1, c_w2, c_b2,
                                          out_pos);
    node_kernel<<<(NN + 127) / 128, 512, ND_SMEM>>>(x, n_w1, n_b1, n_g1, n_be1,
                                                    n_w2, n_b2, out_x);
}

// round 15
// speedup vs baseline: 1.0556x; 1.0556x over previous
#include <cuda_runtime.h>
#include <cuda_bf16.h>
#include <cstdint>

#define NN   50000
#define EE   800000
#define FEAT 128
#define HID  128
#define EPSL 1e-5f

#define ASTR 132          // MMA A-tile stride (floats)
#define BSTR 136          // tf32 weight-tile stride (floats)
#define B2STR 132         // bf16-packed weight-tile stride (uint32 units)
#define ZSTR 68           // bf16-packed z-tile stride (uint32 units)

// ---------------- scratch (device globals) -----------------------------------
__device__ float g_A[NN * FEAT];
__device__ float g_B[NN * FEAT];
__device__ float g_aggm[NN * HID];
__device__ int   g_src[EE];
__device__ int   g_dst[EE];

__device__ __forceinline__ float silu_f(float v) {
    return __fdividef(v, 1.0f + __expf(-v));
}
__device__ __forceinline__ uint32_t f2tf32(float f) {
    uint32_t r; asm("cvt.rna.tf32.f32 %0, %1;" : "=r"(r) : "f"(f)); return r;
}
__device__ __forceinline__ uint32_t packbf2(float lo, float hi) {
    __nv_bfloat162 h = __floats2bfloat162_rn(lo, hi);
    return *(uint32_t*)&h;
}
// column permutation within each 32-block so a thread's 4 B-frag values are contiguous
__device__ __forceinline__ int permn(int n) {
    return (n & ~31) + ((n & 7) << 2) + ((n >> 3) & 3);
}
__device__ __forceinline__ void mma8(float* d, const uint32_t* a, const uint32_t* b) {
    asm volatile("mma.sync.aligned.m16n8k8.row.col.f32.tf32.tf32.f32 "
                 "{%0,%1,%2,%3}, {%4,%5,%6,%7}, {%8,%9}, {%0,%1,%2,%3};"
                 : "+f"(d[0]), "+f"(d[1]), "+f"(d[2]), "+f"(d[3])
                 : "r"(a[0]), "r"(a[1]), "r"(a[2]), "r"(a[3]), "r"(b[0]), "r"(b[1]));
}
__device__ __forceinline__ void mma16bf(float* d, const uint32_t* a, const uint32_t* b) {
    asm volatile("mma.sync.aligned.m16n8k16.row.col.f32.bf16.bf16.f32 "
                 "{%0,%1,%2,%3}, {%4,%5,%6,%7}, {%8,%9}, {%0,%1,%2,%3};"
                 : "+f"(d[0]), "+f"(d[1]), "+f"(d[2]), "+f"(d[3])
                 : "r"(a[0]), "r"(a[1]), "r"(a[2]), "r"(a[3]), "r"(b[0]), "r"(b[1]));
}

// per-warp tf32 GEMM: C[16x32] += A[16x128] * B[128x32]; B n-permuted
__device__ __forceinline__ void warp_gemm1(const uint32_t* __restrict__ Au,
                                           const uint32_t* __restrict__ Bu,
                                           float c[4][4],
                                           int mbase, int nbase, int g, int t)
{
#pragma unroll 1
    for (int ks = 0; ks < 16; ks++) {
        int kk = ks * 8;
        uint32_t af[4];
        {
            const uint32_t* p = Au + (mbase + g) * ASTR + kk + t;
            af[0] = p[0];
            af[1] = p[8 * ASTR];
            af[2] = p[4];
            af[3] = p[8 * ASTR + 4];
        }
        const uint32_t* pb = Bu + (kk + t) * BSTR + nbase + 4 * g;
        uint4 b0 = *(const uint4*)pb;
        uint4 b1 = *(const uint4*)(pb + 4 * BSTR);
        uint32_t bf[4][2] = {{b0.x, b1.x}, {b0.y, b1.y}, {b0.z, b1.z}, {b0.w, b1.w}};
#pragma unroll
        for (int nt = 0; nt < 4; nt++)
            mma8(c[nt], af, bf[nt]);
    }
}

// per-warp bf16 GEMM: C[16x32] += Z[16x128]_bf16 * B[128x32]_bf16 (k-pair packed)
__device__ __forceinline__ void warp_gemm_bf(const uint32_t* __restrict__ Zu,
                                             const uint32_t* __restrict__ Bu,
                                             float c[4][4],
                                             int mbase, int nbase, int g, int t)
{
#pragma unroll 1
    for (int ks = 0; ks < 8; ks++) {
        int kk0 = ks * 8;    // half-index of k0 = ks*16
        uint32_t af[4];
        {
            const uint32_t* p = Zu + (mbase + g) * ZSTR + kk0 + t;
            af[0] = p[0];
            af[1] = p[8 * ZSTR];
            af[2] = p[4];
            af[3] = p[8 * ZSTR + 4];
        }
        const uint32_t* pb = Bu + (kk0 + t) * B2STR + nbase + 4 * g;
        uint4 b0 = *(const uint4*)pb;
        uint4 b1 = *(const uint4*)(pb + 4 * B2STR);
        uint32_t bf[4][2] = {{b0.x, b1.x}, {b0.y, b1.y}, {b0.z, b1.z}, {b0.w, b1.w}};
#pragma unroll
        for (int nt = 0; nt < 4; nt++)
            mma16bf(c[nt], af, bf[nt]);
    }
}

// per-warp tf32 GEMM (512-thr kernels): C[32x32] += A[32x128] * B[128x32]; B n-permuted
__device__ __forceinline__ void warp_gemm2(const uint32_t* __restrict__ Au,
                                           const uint32_t* __restrict__ Bu,
                                           float c[2][4][4],
                                           int mbase, int nbase, int g, int t)
{
#pragma unroll 1
    for (int ks = 0; ks < 16; ks++) {
        int kk = ks * 8;
        uint32_t af[2][4];
#pragma unroll
        for (int mt = 0; mt < 2; mt++) {
            const uint32_t* p = Au + (mbase + mt * 16 + g) * ASTR + kk + t;
            af[mt][0] = p[0];
            af[mt][1] = p[8 * ASTR];
            af[mt][2] = p[4];
            af[mt][3] = p[8 * ASTR + 4];
        }
        const uint32_t* pb = Bu + (kk + t) * BSTR + nbase + 4 * g;
        uint4 b0 = *(const uint4*)pb;
        uint4 b1 = *(const uint4*)(pb + 4 * BSTR);
        uint32_t bf[4][2] = {{b0.x, b1.x}, {b0.y, b1.y}, {b0.z, b1.z}, {b0.w, b1.w}};
#pragma unroll
        for (int mt = 0; mt < 2; mt++)
#pragma unroll
            for (int nt = 0; nt < 4; nt++)
                mma8(c[mt][nt], af[mt], bf[nt]);
    }
}

// ---------------- K-1: normalize edge_index dtype ----------------------------
__global__ void conv_idx_kernel(const void* __restrict__ ei_raw)
{
    const long long* e64 = (const long long*)ei_raw;
    const int*       e32 = (const int*)ei_raw;
    bool is64 = true;
#pragma unroll
    for (int j = 0; j < 8; j++) {
        long long v = e64[j];
        if (v < 0 || v >= NN) is64 = false;
    }
    int i = blockIdx.x * blockDim.x + threadIdx.x;
    int stride = gridDim.x * blockDim.x;
    if (is64) {
        for (int e = i; e < EE; e += stride) {
            g_src[e] = (int)e64[e];
            g_dst[e] = (int)e64[EE + e];
        }
    } else {
        for (int e = i; e < EE; e += stride) {
            g_src[e] = e32[e];
            g_dst[e] = e32[EE + e];
        }
    }
}

// ---------------- K0: zero agg_m, pos_out = pos ------------------------------
__global__ void init_kernel(const float* __restrict__ pos, float* __restrict__ out_pos)
{
    int i = blockIdx.x * blockDim.x + threadIdx.x;
    int stride = gridDim.x * blockDim.x;
    for (int j = i; j < NN * HID; j += stride) g_aggm[j] = 0.0f;
    for (int j = i; j < NN * 3;   j += stride) out_pos[j] = pos[j];
}

// ---------------- K1: A = x@Wa, B = x@Wb (tf32 MMA, 512 thr) ------------------
#define PB_SMEM (51712 * 4)
__global__ __launch_bounds__(512, 1)
void preab_kernel(const float* __restrict__ x, const float* __restrict__ e_w1)
{
    extern __shared__ float sm[];
    float* As  = sm;
    float* B1s = sm + 16896;
    float* B2s = sm + 34304;
    const uint32_t* Au  = (const uint32_t*)As;
    const uint32_t* B1u = (const uint32_t*)B1s;
    const uint32_t* B2u = (const uint32_t*)B2s;

    int tid = threadIdx.x, warp = tid >> 5, lane = tid & 31;
    int g = lane >> 2, t = lane & 3;
    int wm = warp >> 2, wn = warp & 3;
    int mbase = wm * 32, nbase = wn * 32;
    int n0 = blockIdx.x * 128;

    for (int idx = tid; idx < 16384; idx += 512) {
        int row = idx >> 7, k = idx & 127;
        float v = (n0 + row < NN) ? x[(size_t)(n0 + row) * 128 + k] : 0.f;
        As[row * ASTR + k]  = __uint_as_float(f2tf32(v));
        int kp = permn(k);
        B1s[row * BSTR + kp] = __uint_as_float(f2tf32(e_w1[row * 128 + k]));
        B2s[row * BSTR + kp] = __uint_as_float(f2tf32(e_w1[(128 + row) * 128 + k]));
    }
    __syncthreads();

    float c[2][4][4];
#pragma unroll
    for (int mt = 0; mt < 2; mt++)
#pragma unroll
        for (int nt = 0; nt < 4; nt++)
#pragma unroll
            for (int j = 0; j < 4; j++) c[mt][nt][j] = 0.f;
    warp_gemm2(Au, B1u, c, mbase, nbase, g, t);
#pragma unroll
    for (int mt = 0; mt < 2; mt++) {
        int r0 = mbase + mt * 16 + g, r1 = r0 + 8;
#pragma unroll
        for (int nt = 0; nt < 4; nt++) {
            int c0 = nbase + nt * 8 + 2 * t;
            if (n0 + r0 < NN)
                *(float2*)(g_A + (size_t)(n0 + r0) * 128 + c0) = make_float2(c[mt][nt][0], c[mt][nt][1]);
            if (n0 + r1 < NN)
                *(float2*)(g_A + (size_t)(n0 + r1) * 128 + c0) = make_float2(c[mt][nt][2], c[mt][nt][3]);
        }
    }

#pragma unroll
    for (int mt = 0; mt < 2; mt++)
#pragma unroll
        for (int nt = 0; nt < 4; nt++)
#pragma unroll
            for (int j = 0; j < 4; j++) c[mt][nt][j] = 0.f;
    warp_gemm2(Au, B2u, c, mbase, nbase, g, t);
#pragma unroll
    for (int mt = 0; mt < 2; mt++) {
        int r0 = mbase + mt * 16 + g, r1 = r0 + 8;
#pragma unroll
        for (int nt = 0; nt < 4; nt++) {
            int c0 = nbase + nt * 8 + 2 * t;
            if (n0 + r0 < NN)
                *(float2*)(g_B + (size_t)(n0 + r0) * 128 + c0) = make_float2(c[mt][nt][0], c[mt][nt][1]);
            if (n0 + r1 < NN)
                *(float2*)(g_B + (size_t)(n0 + r1) * 128 + c0) = make_float2(c[mt][nt][2], c[mt][nt][3]);
        }
    }
}

// ---------------- K2: persistent edge kernel ----------------------------------
// Two independent 512-thread groups; GEMM1 tf32, GEMM2 bf16 (coef path).
#define EO_A    0                       // 2 groups x 64 x ASTR = 16896
#define EO_B1   16896                   // tf32, 128*BSTR = 17408
#define EO_B2   34304                   // bf16-packed, 64*B2STR = 8448
#define EO_SV   42752                   // shared constants (1408 floats)
#define EO_GRP  44160                   // per-group scratch, 1408 floats each
// shared const indices (relative to sv)
#define SV_WC0  0
#define SV_WC1  128
#define SV_WD   256
#define SV_B1   384
#define SV_I1   512    // interleaved (u1, vb1) pairs
#define SV_IG   768    // interleaved (g2, be2) pairs
#define SV_I2   1024   // interleaved (u2, vb2) pairs
#define SV_CW2  1280
// per-group indices (relative to gsv)
#define GV_RELX 0
#define GV_RELY 64
#define GV_RELZ 128
#define GV_R2   192
#define GV_EA0  256
#define GV_EA1  320
#define GV_MU1  384
#define GV_RS1  448
#define GV_SUM  512    // [64][4]
#define GV_SQ   768    // [64][4]
#define GV_SUM2 1024   // [64][4]
#define GV_IDX  1280   // ints: 64 dst, 64 src
#define GRP_FLOATS 1408
#define EDGE_SMEM ((EO_GRP + 2 * GRP_FLOATS) * 4)   // 187904 bytes

#define BARG(id) asm volatile("bar.sync %0, 512;" :: "r"(id) : "memory")

__global__ __launch_bounds__(1024, 1)
void edge_kernel(const float* __restrict__ pos,
                 const float* __restrict__ ea,
                 const float* __restrict__ e_w1, const float* __restrict__ e_b1,
                 const float* __restrict__ e_g1, const float* __restrict__ e_be1,
                 const float* __restrict__ e_w2, const float* __restrict__ e_b2,
                 const float* __restrict__ e_g2, const float* __restrict__ e_be2,
                 const float* __restrict__ c_w1, const float* __restrict__ c_b1,
                 const float* __restrict__ c_w2, const float* __restrict__ c_b2,
                 float* __restrict__ out_pos)
{
    extern __shared__ float sm[];
    float* B1s = sm + EO_B1;
    uint32_t* B2h = (uint32_t*)(sm + EO_B2);
    float* sv  = sm + EO_SV;
    const uint32_t* B1u = (const uint32_t*)B1s;

    int tid = threadIdx.x, warp = tid >> 5, lane = tid & 31;
    int gid = warp >> 4;
    int wig = warp & 15;
    int gtid = tid & 511;
    int bar = gid + 1;
    int g = lane >> 2, t = lane & 3;
    int wm = wig >> 2, wn = wig & 3;
    int mbase = wm * 16, nbase = wn * 32;

    float* As  = sm + EO_A + gid * (64 * ASTR);
    float* gsv = sm + EO_GRP + gid * GRP_FLOATS;
    int*   gdst = (int*)(gsv + GV_IDX);
    int*   gsrc = gdst + 64;
    const uint32_t* Au = (const uint32_t*)As;
    uint32_t* Zu = (uint32_t*)As;          // bf16-packed z, aliases dead A region

    // ---- stage weights + shared constants ----
    for (int idx = tid; idx < 16384; idx += 1024) {
        int k = idx >> 7, n = idx & 127;
        B1s[k * BSTR + permn(n)] = __uint_as_float(f2tf32(e_g1[k] * e_w2[k * 128 + n]));
    }
    for (int idx = tid; idx < 8192; idx += 1024) {
        int kk = idx >> 7, n = idx & 127;
        float v0 = e_g2[2 * kk]     * c_w1[(2 * kk) * 128 + n];
        float v1 = e_g2[2 * kk + 1] * c_w1[(2 * kk + 1) * 128 + n];
        B2h[kk * B2STR + permn(n)] = packbf2(v0, v1);
    }
    if (tid < 128) {
        sv[SV_WC0 + tid] = e_w1[256 * 128 + tid];
        sv[SV_WC1 + tid] = e_w1[257 * 128 + tid];
        sv[SV_WD  + tid] = e_w1[258 * 128 + tid];
        sv[SV_B1  + tid] = e_b1[tid];
        sv[SV_IG  + 2 * tid]     = e_g2[tid];
        sv[SV_IG  + 2 * tid + 1] = e_be2[tid];
        sv[SV_CW2 + tid] = c_w2[tid];
    }
    if (tid < 512) {
        int quad = tid >> 7, n = tid & 127;
        float acc = 0.f;
        if (quad == 0) {
            for (int k = 0; k < 128; k++) acc += e_g1[k] * e_w2[k * 128 + n];
            sv[SV_I1 + 2 * n] = acc;
        } else if (quad == 1) {
            for (int k = 0; k < 128; k++) acc += e_be1[k] * e_w2[k * 128 + n];
            sv[SV_I1 + 2 * n + 1] = acc + e_b2[n];
        } else if (quad == 2) {
            for (int k = 0; k < 128; k++) acc += e_g2[k] * c_w1[k * 128 + n];
            sv[SV_I2 + 2 * n] = acc;
        } else {
            for (int k = 0; k < 128; k++) acc += e_be2[k] * c_w1[k * 128 + n];
            sv[SV_I2 + 2 * n + 1] = acc + c_b1[n];
        }
    }
    float cb2 = c_b2[0];
    __syncthreads();

    int k4 = lane * 4;
    bool first = true;

    const int ntiles = EE / 64;
    for (int tile = blockIdx.x * 2 + gid; tile < ntiles; tile += 2 * gridDim.x) {
        int e0 = tile * 64;
        // ---- phase A (gtid<64): prev-tile pos atomics + stage edge meta ----
        if (gtid < 64) {
            if (!first) {
                float coef = gsv[GV_SUM2 + gtid * 4] + gsv[GV_SUM2 + gtid * 4 + 1]
                           + gsv[GV_SUM2 + gtid * 4 + 2] + gsv[GV_SUM2 + gtid * 4 + 3] + cb2;
                int dip = gdst[gtid];
                atomicAdd(&out_pos[dip * 3 + 0], gsv[GV_RELX + gtid] * coef);
                atomicAdd(&out_pos[dip * 3 + 1], gsv[GV_RELY + gtid] * coef);
                atomicAdd(&out_pos[dip * 3 + 2], gsv[GV_RELZ + gtid] * coef);
            }
            int e = e0 + gtid;
            int si = g_src[e], di = g_dst[e];
            float rx = pos[di * 3 + 0] - pos[si * 3 + 0];
            float ry = pos[di * 3 + 1] - pos[si * 3 + 1];
            float rz = pos[di * 3 + 2] - pos[si * 3 + 2];
            gsrc[gtid] = si; gdst[gtid] = di;
            gsv[GV_RELX + gtid] = rx; gsv[GV_RELY + gtid] = ry; gsv[GV_RELZ + gtid] = rz;
            gsv[GV_R2 + gtid]  = rx * rx + ry * ry + rz * rz;
            gsv[GV_EA0 + gtid] = ea[2 * e];
            gsv[GV_EA1 + gtid] = ea[2 * e + 1];
        }
        first = false;
        BARG(bar);

        // ---- layer-1: gather + SiLU -> As (raw h, tf32); row stats ----
        {
            float4 wc0 = *(const float4*)(sv + SV_WC0 + k4);
            float4 wc1 = *(const float4*)(sv + SV_WC1 + k4);
            float4 wdv = *(const float4*)(sv + SV_WD  + k4);
            float4 b1v = *(const float4*)(sv + SV_B1  + k4);
#pragma unroll 2
            for (int r = 0; r < 4; r++) {
                int row = wig * 4 + r;
                int si = gsrc[row], di = gdst[row];
                float4 a = *(const float4*)(g_A + (size_t)si * 128 + k4);
                float4 b = *(const float4*)(g_B + (size_t)di * 128 + k4);
                float e0v = gsv[GV_EA0 + row], e1v = gsv[GV_EA1 + row], r2v = gsv[GV_R2 + row];
                float4 o;
                o.x = silu_f(a.x + b.x + e0v * wc0.x + e1v * wc1.x + r2v * wdv.x + b1v.x);
                o.y = silu_f(a.y + b.y + e0v * wc0.y + e1v * wc1.y + r2v * wdv.y + b1v.y);
                o.z = silu_f(a.z + b.z + e0v * wc0.z + e1v * wc1.z + r2v * wdv.z + b1v.z);
                o.w = silu_f(a.w + b.w + e0v * wc0.w + e1v * wc1.w + r2v * wdv.w + b1v.w);
                float s = o.x + o.y + o.z + o.w;
                float q = o.x * o.x + o.y * o.y + o.z * o.z + o.w * o.w;
#pragma unroll
                for (int off = 16; off > 0; off >>= 1) {
                    s += __shfl_xor_sync(0xffffffffu, s, off);
                    q += __shfl_xor_sync(0xffffffffu, q, off);
                }
                uint4 tv;
                tv.x = f2tf32(o.x); tv.y = f2tf32(o.y);
                tv.z = f2tf32(o.z); tv.w = f2tf32(o.w);
                *(uint4*)(As + row * ASTR + k4) = tv;
                if (lane == 0) {
                    float mu = s * (1.0f / 128.0f);
                    gsv[GV_MU1 + row] = mu;
                    gsv[GV_RS1 + row] = rsqrtf(q * (1.0f / 128.0f) - mu * mu + EPSL);
                }
            }
        }
        BARG(bar);

        // ---- GEMM1: h @ (g1 ∘ e_w2), tf32 ----
        float c[4][4];
#pragma unroll
        for (int nt = 0; nt < 4; nt++)
#pragma unroll
            for (int j = 0; j < 4; j++) c[nt][j] = 0.f;
        warp_gemm1(Au, B1u, c, mbase, nbase, g, t);
        BARG(bar);

        // ---- ep1: y = rs1*(d - mu1*u1) + vb1 ; z = silu(y) -> Z (bf16) + partials ----
        {
            int r0 = mbase + g, r1 = r0 + 8;
            float rsA = gsv[GV_RS1 + r0], bA = rsA * gsv[GV_MU1 + r0];
            float rsB = gsv[GV_RS1 + r1], bB = rsB * gsv[GV_MU1 + r1];
            float s0 = 0.f, q0 = 0.f, s1 = 0.f, q1 = 0.f;
#pragma unroll
            for (int nt = 0; nt < 4; nt++) {
                int c0 = nbase + nt * 8 + 2 * t;
                float4 P = *(const float4*)(sv + SV_I1 + 2 * c0);   // u1a, vba, u1b, vbb
                float z0 = silu_f(rsA * c[nt][0] - bA * P.x + P.y);
                float z1 = silu_f(rsA * c[nt][1] - bA * P.z + P.w);
                float z2 = silu_f(rsB * c[nt][2] - bB * P.x + P.y);
                float z3 = silu_f(rsB * c[nt][3] - bB * P.z + P.w);
                c[nt][0] = z0; c[nt][1] = z1; c[nt][2] = z2; c[nt][3] = z3;
                Zu[r0 * ZSTR + (c0 >> 1)] = packbf2(z0, z1);
                Zu[r1 * ZSTR + (c0 >> 1)] = packbf2(z2, z3);
                s0 += z0 + z1; q0 += z0 * z0 + z1 * z1;
                s1 += z2 + z3; q1 += z2 * z2 + z3 * z3;
            }
#pragma unroll
            for (int off = 1; off <= 2; off <<= 1) {
                s0 += __shfl_xor_sync(0xffffffffu, s0, off);
                s1 += __shfl_xor_sync(0xffffffffu, s1, off);
                q0 += __shfl_xor_sync(0xffffffffu, q0, off);
                q1 += __shfl_xor_sync(0xffffffffu, q1, off);
            }
            if (t == 0) {
                gsv[GV_SUM + r0 * 4 + wn] = s0;
                gsv[GV_SQ  + r0 * 4 + wn] = q0;
                gsv[GV_SUM + r1 * 4 + wn] = s1;
                gsv[GV_SQ  + r1 * 4 + wn] = q1;
            }
        }
        BARG(bar);

        // ---- phase B: local LN2 stats, aggm atomics, GEMM2 (bf16), ep2 ----
        {
            int r0 = mbase + g, r1 = r0 + 8;
            float s0 = gsv[GV_SUM + r0 * 4] + gsv[GV_SUM + r0 * 4 + 1]
                     + gsv[GV_SUM + r0 * 4 + 2] + gsv[GV_SUM + r0 * 4 + 3];
            float q0 = gsv[GV_SQ + r0 * 4] + gsv[GV_SQ + r0 * 4 + 1]
                     + gsv[GV_SQ + r0 * 4 + 2] + gsv[GV_SQ + r0 * 4 + 3];
            float s1 = gsv[GV_SUM + r1 * 4] + gsv[GV_SUM + r1 * 4 + 1]
                     + gsv[GV_SUM + r1 * 4 + 2] + gsv[GV_SUM + r1 * 4 + 3];
            float q1 = gsv[GV_SQ + r1 * 4] + gsv[GV_SQ + r1 * 4 + 1]
                     + gsv[GV_SQ + r1 * 4 + 2] + gsv[GV_SQ + r1 * 4 + 3];
            float mu0 = s0 * (1.0f / 128.0f);
            float rs0 = rsqrtf(q0 * (1.0f / 128.0f) - mu0 * mu0 + EPSL);
            float mu1 = s1 * (1.0f / 128.0f);
            float rs1 = rsqrtf(q1 * (1.0f / 128.0f) - mu1 * mu1 + EPSL);

            int d0 = gdst[r0], d1 = gdst[r1];
#pragma unroll
            for (int nt = 0; nt < 4; nt++) {
                int c0 = nbase + nt * 8 + 2 * t;
                float4 G = *(const float4*)(sv + SV_IG + 2 * c0);   // g2a, bea, g2b, beb
                float m0 = (c[nt][0] - mu0) * rs0 * G.x + G.y;
                float m1 = (c[nt][1] - mu0) * rs0 * G.z + G.w;
                float m2 = (c[nt][2] - mu1) * rs1 * G.x + G.y;
                float m3 = (c[nt][3] - mu1) * rs1 * G.z + G.w;
                asm volatile("red.global.add.v2.f32 [%0], {%1, %2};"
                             :: "l"(g_aggm + (size_t)d0 * 128 + c0), "f"(m0), "f"(m1) : "memory");
                asm volatile("red.global.add.v2.f32 [%0], {%1, %2};"
                             :: "l"(g_aggm + (size_t)d1 * 128 + c0), "f"(m2), "f"(m3) : "memory");
            }

            // GEMM2: z @ (g2 ∘ c_w1), bf16 m16n8k16
#pragma unroll
            for (int nt = 0; nt < 4; nt++)
#pragma unroll
                for (int j = 0; j < 4; j++) c[nt][j] = 0.f;
            warp_gemm_bf(Zu, B2h, c, mbase, nbase, g, t);

            // ep2: val = rs*(d - mu*u2) + vb2 ; coef partials -> SUM2
            float b0 = rs0 * mu0, b1 = rs1 * mu1;
            float p0 = 0.f, p1 = 0.f;
#pragma unroll
            for (int nt = 0; nt < 4; nt++) {
                int c0 = nbase + nt * 8 + 2 * t;
                float4 Q = *(const float4*)(sv + SV_I2 + 2 * c0);   // u2a, vba, u2b, vbb
                float2 W = *(const float2*)(sv + SV_CW2 + c0);
                p0 += silu_f(rs0 * c[nt][0] - b0 * Q.x + Q.y) * W.x
                    + silu_f(rs0 * c[nt][1] - b0 * Q.z + Q.w) * W.y;
                p1 += silu_f(rs1 * c[nt][2] - b1 * Q.x + Q.y) * W.x
                    + silu_f(rs1 * c[nt][3] - b1 * Q.z + Q.w) * W.y;
            }
#pragma unroll
            for (int off = 1; off <= 2; off <<= 1) {
                p0 += __shfl_xor_sync(0xffffffffu, p0, off);
                p1 += __shfl_xor_sync(0xffffffffu, p1, off);
            }
            if (t == 0) {
                gsv[GV_SUM2 + r0 * 4 + wn] = p0;
                gsv[GV_SUM2 + r1 * 4 + wn] = p1;
            }
        }
        BARG(bar);
    }

    // ---- final tile's pos atomics (per group) ----
    if (!first && gtid < 64) {
        float coef = gsv[GV_SUM2 + gtid * 4] + gsv[GV_SUM2 + gtid * 4 + 1]
                   + gsv[GV_SUM2 + gtid * 4 + 2] + gsv[GV_SUM2 + gtid * 4 + 3] + cb2;
        int di = gdst[gtid];
        atomicAdd(&out_pos[di * 3 + 0], gsv[GV_RELX + gtid] * coef);
        atomicAdd(&out_pos[di * 3 + 1], gsv[GV_RELY + gtid] * coef);
        atomicAdd(&out_pos[di * 3 + 2], gsv[GV_RELZ + gtid] * coef);
    }
}

// ---------------- K3: node MLP + residual (tf32 MMA, 512 thr) ----------------
#define NV_B1   0
#define NV_I    128    // interleaved (u, vb) pairs
#define NV_MU   384
#define NV_RS   512
#define NV_SUM  640    // [128][4]
#define NV_SQ   1152   // [128][4]
#define NV_FLOATS 1664
#define ND_SMEM ((34304 + NV_FLOATS) * 4)
__global__ __launch_bounds__(512, 1)
void node_kernel(const float* __restrict__ x,
                 const float* __restrict__ n_w1, const float* __restrict__ n_b1,
                 const float* __restrict__ n_g1, const float* __restrict__ n_be1,
                 const float* __restrict__ n_w2, const float* __restrict__ n_b2,
                 float* __restrict__ out_x)
{
    extern __shared__ float sm[];
    float* As = sm;
    float* Bs = sm + 16896;
    float* sv = sm + 34304;
    const uint32_t* Au = (const uint32_t*)As;
    const uint32_t* Bu = (const uint32_t*)Bs;

    int tid = threadIdx.x, warp = tid >> 5, lane = tid & 31;
    int g = lane >> 2, t = lane & 3;
    int wm = warp >> 2, wn = warp & 3;
    int mbase = wm * 32, nbase = wn * 32;
    int n0 = blockIdx.x * 128;

    if (tid < 128) sv[NV_B1 + tid] = n_b1[tid];
    if (tid >= 128 && tid < 384) {
        int half = (tid - 128) >> 7, n = tid & 127;
        float acc = 0.f;
        if (half == 0) {
            for (int k = 0; k < 128; k++) acc += n_g1[k] * n_w2[k * 128 + n];
            sv[NV_I + 2 * n] = acc;
        } else {
            for (int k = 0; k < 128; k++) acc += n_be1[k] * n_w2[k * 128 + n];
            sv[NV_I + 2 * n + 1] = acc + n_b2[n];
        }
    }

    // phase 1: x @ W1a
    for (int idx = tid; idx < 16384; idx += 512) {
        int row = idx >> 7, k = idx & 127;
        float v = (n0 + row < NN) ? x[(size_t)(n0 + row) * 128 + k] : 0.f;
        As[row * ASTR + k] = __uint_as_float(f2tf32(v));
        Bs[row * BSTR + permn(k)] = __uint_as_float(f2tf32(n_w1[row * 128 + k]));
    }
    __syncthreads();

    float c[2][4][4];
#pragma unroll
    for (int mt = 0; mt < 2; mt++)
#pragma unroll
        for (int nt = 0; nt < 4; nt++)
#pragma unroll
            for (int j = 0; j < 4; j++) c[mt][nt][j] = 0.f;
    warp_gemm2(Au, Bu, c, mbase, nbase, g, t);
    __syncthreads();

    // phase 2: + aggm @ W1b
    for (int idx = tid; idx < 16384; idx += 512) {
        int row = idx >> 7, k = idx & 127;
        float v = (n0 + row < NN) ? g_aggm[(size_t)(n0 + row) * 128 + k] : 0.f;
        As[row * ASTR + k] = __uint_as_float(f2tf32(v));
        Bs[row * BSTR + permn(k)] = __uint_as_float(f2tf32(n_w1[(128 + row) * 128 + k]));
    }
    __syncthreads();
    warp_gemm2(Au, Bu, c, mbase, nbase, g, t);
    __syncthreads();

    // ep1: z = silu(acc + b1) -> As (tf32) + row stats
#pragma unroll
    for (int mt = 0; mt < 2; mt++) {
        int r0 = mbase + mt * 16 + g, r1 = r0 + 8;
        float s0 = 0.f, q0 = 0.f, s1 = 0.f, q1 = 0.f;
#pragma unroll
        for (int nt = 0; nt < 4; nt++) {
            int c0 = nbase + nt * 8 + 2 * t;
            float ba = sv[NV_B1 + c0], bb = sv[NV_B1 + c0 + 1];
            float z0 = silu_f(c[mt][nt][0] + ba);
            float z1 = silu_f(c[mt][nt][1] + bb);
            float z2 = silu_f(c[mt][nt][2] + ba);
            float z3 = silu_f(c[mt][nt][3] + bb);
            uint2 p0; p0.x = f2tf32(z0); p0.y = f2tf32(z1);
            uint2 p1; p1.x = f2tf32(z2); p1.y = f2tf32(z3);
            *(uint2*)(As + r0 * ASTR + c0) = p0;
            *(uint2*)(As + r1 * ASTR + c0) = p1;
            s0 += z0 + z1; q0 += z0 * z0 + z1 * z1;
            s1 += z2 + z3; q1 += z2 * z2 + z3 * z3;
        }
#pragma unroll
        for (int off = 1; off <= 2; off <<= 1) {
            s0 += __shfl_xor_sync(0xffffffffu, s0, off);
            s1 += __shfl_xor_sync(0xffffffffu, s1, off);
            q0 += __shfl_xor_sync(0xffffffffu, q0, off);
            q1 += __shfl_xor_sync(0xffffffffu, q1, off);
        }
        if (t == 0) {
            sv[NV_SUM + r0 * 4 + wn] = s0;
            sv[NV_SQ  + r0 * 4 + wn] = q0;
            sv[NV_SUM + r1 * 4 + wn] = s1;
            sv[NV_SQ  + r1 * 4 + wn] = q1;
        }
    }
    __syncthreads();
    if (tid < 128) {
        float s = sv[NV_SUM + tid * 4] + sv[NV_SUM + tid * 4 + 1]
                + sv[NV_SUM + tid * 4 + 2] + sv[NV_SUM + tid * 4 + 3];
        float q = sv[NV_SQ + tid * 4] + sv[NV_SQ + tid * 4 + 1]
                + sv[NV_SQ + tid * 4 + 2] + sv[NV_SQ + tid * 4 + 3];
        float mu = s * (1.0f / 128.0f);
        sv[NV_MU + tid] = mu;
        sv[NV_RS + tid] = rsqrtf(q * (1.0f / 128.0f) - mu * mu + EPSL);
    }
    // stage (g1 ∘ W2) into Bs (n-permuted)
    for (int idx = tid; idx < 16384; idx += 512) {
        int k = idx >> 7, n = idx & 127;
        Bs[k * BSTR + permn(n)] = __uint_as_float(f2tf32(n_g1[k] * n_w2[k * 128 + n]));
    }
    __syncthreads();

    // GEMM2: z @ (g1 ∘ W2)
#pragma unroll
    for (int mt = 0; mt < 2; mt++)
#pragma unroll
        for (int nt = 0; nt < 4; nt++)
#pragma unroll
            for (int j = 0; j < 4; j++) c[mt][nt][j] = 0.f;
    warp_gemm2(Au, Bu, c, mbase, nbase, g, t);

    // ep2: out = x + rs*d - rs*mu*u + vb
#pragma unroll
    for (int mt = 0; mt < 2; mt++) {
        int r0 = mbase + mt * 16 + g, r1 = r0 + 8;
        float rs0 = sv[NV_RS + r0], b0 = rs0 * sv[NV_MU + r0];
        float rs1 = sv[NV_RS + r1], b1 = rs1 * sv[NV_MU + r1];
#pragma unroll
        for (int nt = 0; nt < 4; nt++) {
            int c0 = nbase + nt * 8 + 2 * t;
            float4 Q = *(const float4*)(sv + NV_I + 2 * c0);   // ua, va, ub, vb
            if (n0 + r0 < NN) {
                float2 xv = *(const float2*)(x + (size_t)(n0 + r0) * 128 + c0);
                *(float2*)(out_x + (size_t)(n0 + r0) * 128 + c0) =
                    make_float2(xv.x + rs0 * c[mt][nt][0] - b0 * Q.x + Q.y,
                                xv.y + rs0 * c[mt][nt][1] - b0 * Q.z + Q.w);
            }
            if (n0 + r1 < NN) {
                float2 xv = *(const float2*)(x + (size_t)(n0 + r1) * 128 + c0);
                *(float2*)(out_x + (size_t)(n0 + r1) * 128 + c0) =
                    make_float2(xv.x + rs1 * c[mt][nt][2] - b1 * Q.x + Q.y,
                                xv.y + rs1 * c[mt][nt][3] - b1 * Q.z + Q.w);
            }
        }
    }
}

// ---------------- launch ------------------------------------------------------
extern "C" void kernel_launch(void* const* d_in, const int* in_sizes, int n_in,
                              void* d_out, int out_size)
{
    const float*     x     = (const float*)d_in[0];
    const float*     pos   = (const float*)d_in[1];
    const void*      ei    = d_in[2];
    const float*     ea    = (const float*)d_in[3];
    const float*     e_w1  = (const float*)d_in[4];
    const float*     e_b1  = (const float*)d_in[5];
    const float*     e_g1  = (const float*)d_in[6];
    const float*     e_be1 = (const float*)d_in[7];
    const float*     e_w2  = (const float*)d_in[8];
    const float*     e_b2  = (const float*)d_in[9];
    const float*     e_g2  = (const float*)d_in[10];
    const float*     e_be2 = (const float*)d_in[11];
    const float*     n_w1  = (const float*)d_in[12];
    const float*     n_b1  = (const float*)d_in[13];
    const float*     n_g1  = (const float*)d_in[14];
    const float*     n_be1 = (const float*)d_in[15];
    const float*     n_w2  = (const float*)d_in[16];
    const float*     n_b2  = (const float*)d_in[17];
    const float*     c_w1  = (const float*)d_in[18];
    const float*     c_b1  = (const float*)d_in[19];
    const float*     c_w2  = (const float*)d_in[20];
    const float*     c_b2  = (const float*)d_in[21];

    float* out_x   = (float*)d_out;
    float* out_pos = (float*)d_out + (size_t)NN * FEAT;

    cudaFuncSetAttribute(preab_kernel, cudaFuncAttributeMaxDynamicSharedMemorySize, PB_SMEM);
    cudaFuncSetAttribute(edge_kernel,  cudaFuncAttributeMaxDynamicSharedMemorySize, EDGE_SMEM);
    cudaFuncSetAttribute(node_kernel,  cudaFuncAttributeMaxDynamicSharedMemorySize, ND_SMEM);

    conv_idx_kernel<<<256, 256>>>(ei);
    init_kernel<<<256, 256>>>(pos, out_pos);
    preab_kernel<<<(NN + 127) / 128, 512, PB_SMEM>>>(x, e_w1);
    edge_kernel<<<148, 1024, EDGE_SMEM>>>(pos, ea,
                                          e_w1, e_b1, e_g1, e_be1,
                                          e_w2, e_b2, e_g2, e_be2,
                                          c_w1, c_b1, c_w2, c_b2,
                                          out_pos);
    node_kernel<<<(NN + 127) / 128, 512, ND_SMEM>>>(x, n_w1, n_b1, n_g1, n_be1,
                                                    n_w2, n_b2, out_x);
}

// round 17
// speedup vs baseline: 1.0731x; 1.0166x over previous
#include <cuda_runtime.h>
#include <cuda_bf16.h>
#include <cstdint>

#define NN   50000
#define EE   800000
#define FEAT 128
#define HID  128
#define EPSL 1e-5f

#define ASTR 132          // MMA A-tile stride (floats) for unpaired kernels
#define BSTR 136          // tf32 weight-tile stride (floats)
#define B2STR 132         // bf16-packed weight-tile stride (uint32 units)
#define ZSTR 68           // bf16-packed z-tile stride (uint32 units)
#define APBLK 264         // paired-A block stride (floats) = 132 dwords

// ---------------- scratch (device globals) -----------------------------------
__device__ float g_A[NN * FEAT];
__device__ float g_B[NN * FEAT];
__device__ float g_aggm[NN * HID];
__device__ int   g_src[EE];
__device__ int   g_dst[EE];

__device__ __forceinline__ float silu_f(float v) {
    return __fdividef(v, 1.0f + __expf(-v));
}
__device__ __forceinline__ uint32_t f2tf32(float f) {
    uint32_t r; asm("cvt.rna.tf32.f32 %0, %1;" : "=r"(r) : "f"(f)); return r;
}
__device__ __forceinline__ uint32_t packbf2(float lo, float hi) {
    __nv_bfloat162 h = __floats2bfloat162_rn(lo, hi);
    return *(uint32_t*)&h;
}
// column permutation within each 32-block so a thread's 4 B-frag values are contiguous
__device__ __forceinline__ int permn(int n) {
    return (n & ~31) + ((n & 7) << 2) + ((n >> 3) & 3);
}
__device__ __forceinline__ void mma8(float* d, const uint32_t* a, const uint32_t* b) {
    asm volatile("mma.sync.aligned.m16n8k8.row.col.f32.tf32.tf32.f32 "
                 "{%0,%1,%2,%3}, {%4,%5,%6,%7}, {%8,%9}, {%0,%1,%2,%3};"
                 : "+f"(d[0]), "+f"(d[1]), "+f"(d[2]), "+f"(d[3])
                 : "r"(a[0]), "r"(a[1]), "r"(a[2]), "r"(a[3]), "r"(b[0]), "r"(b[1]));
}
__device__ __forceinline__ void mma16bf(float* d, const uint32_t* a, const uint32_t* b) {
    asm volatile("mma.sync.aligned.m16n8k16.row.col.f32.bf16.bf16.f32 "
                 "{%0,%1,%2,%3}, {%4,%5,%6,%7}, {%8,%9}, {%0,%1,%2,%3};"
                 : "+f"(d[0]), "+f"(d[1]), "+f"(d[2]), "+f"(d[3])
                 : "r"(a[0]), "r"(a[1]), "r"(a[2]), "r"(a[3]), "r"(b[0]), "r"(b[1]));
}

// per-warp tf32 GEMM, paired-A: C[16x32] += A[16x128] * B[128x32]
// A in row-pair-interleaved blocks of 132 dwords; B n-permuted.
__device__ __forceinline__ void warp_gemm1p(const uint64_t* __restrict__ Ap,
                                            const uint32_t* __restrict__ Bu,
                                            float c[4][4],
                                            int wm, int nbase, int g, int t)
{
    const uint64_t* pa = Ap + (wm * 8 + g) * 132 + t;
#pragma unroll 1
    for (int ks = 0; ks < 16; ks++) {
        int kk = ks * 8;
        uint64_t v01 = pa[kk];
        uint64_t v23 = pa[kk + 4];
        uint32_t af[4] = {(uint32_t)v01, (uint32_t)(v01 >> 32),
                          (uint32_t)v23, (uint32_t)(v23 >> 32)};
        const uint32_t* pb = Bu + (kk + t) * BSTR + nbase + 4 * g;
        uint4 b0 = *(const uint4*)pb;
        uint4 b1 = *(const uint4*)(pb + 4 * BSTR);
        uint32_t bf[4][2] = {{b0.x, b1.x}, {b0.y, b1.y}, {b0.z, b1.z}, {b0.w, b1.w}};
#pragma unroll
        for (int nt = 0; nt < 4; nt++)
            mma8(c[nt], af, bf[nt]);
    }
}

// per-warp bf16 GEMM: C[16x32] += Z[16x128]_bf16 * B[128x32]_bf16 (k-pair packed)
__device__ __forceinline__ void warp_gemm_bf(const uint32_t* __restrict__ Zu,
                                             const uint32_t* __restrict__ Bu,
                                             float c[4][4],
                                             int mbase, int nbase, int g, int t)
{
#pragma unroll 1
    for (int ks = 0; ks < 8; ks++) {
        int kk0 = ks * 8;    // half-index of k0 = ks*16
        uint32_t af[4];
        {
            const uint32_t* p = Zu + (mbase + g) * ZSTR + kk0 + t;
            af[0] = p[0];
            af[1] = p[8 * ZSTR];
            af[2] = p[4];
            af[3] = p[8 * ZSTR + 4];
        }
        const uint32_t* pb = Bu + (kk0 + t) * B2STR + nbase + 4 * g;
        uint4 b0 = *(const uint4*)pb;
        uint4 b1 = *(const uint4*)(pb + 4 * B2STR);
        uint32_t bf[4][2] = {{b0.x, b1.x}, {b0.y, b1.y}, {b0.z, b1.z}, {b0.w, b1.w}};
#pragma unroll
        for (int nt = 0; nt < 4; nt++)
            mma16bf(c[nt], af, bf[nt]);
    }
}

// per-warp tf32 GEMM (512-thr kernels): C[32x32] += A[32x128] * B[128x32]; B n-permuted
__device__ __forceinline__ void warp_gemm2(const uint32_t* __restrict__ Au,
                                           const uint32_t* __restrict__ Bu,
                                           float c[2][4][4],
                                           int mbase, int nbase, int g, int t)
{
#pragma unroll 1
    for (int ks = 0; ks < 16; ks++) {
        int kk = ks * 8;
        uint32_t af[2][4];
#pragma unroll
        for (int mt = 0; mt < 2; mt++) {
            const uint32_t* p = Au + (mbase + mt * 16 + g) * ASTR + kk + t;
            af[mt][0] = p[0];
            af[mt][1] = p[8 * ASTR];
            af[mt][2] = p[4];
            af[mt][3] = p[8 * ASTR + 4];
        }
        const uint32_t* pb = Bu + (kk + t) * BSTR + nbase + 4 * g;
        uint4 b0 = *(const uint4*)pb;
        uint4 b1 = *(const uint4*)(pb + 4 * BSTR);
        uint32_t bf[4][2] = {{b0.x, b1.x}, {b0.y, b1.y}, {b0.z, b1.z}, {b0.w, b1.w}};
#pragma unroll
        for (int mt = 0; mt < 2; mt++)
#pragma unroll
            for (int nt = 0; nt < 4; nt++)
                mma8(c[mt][nt], af[mt], bf[nt]);
    }
}

// ---------------- K-1: normalize edge_index dtype ----------------------------
__global__ void conv_idx_kernel(const void* __restrict__ ei_raw)
{
    const long long* e64 = (const long long*)ei_raw;
    const int*       e32 = (const int*)ei_raw;
    bool is64 = true;
#pragma unroll
    for (int j = 0; j < 8; j++) {
        long long v = e64[j];
        if (v < 0 || v >= NN) is64 = false;
    }
    int i = blockIdx.x * blockDim.x + threadIdx.x;
    int stride = gridDim.x * blockDim.x;
    if (is64) {
        for (int e = i; e < EE; e += stride) {
            g_src[e] = (int)e64[e];
            g_dst[e] = (int)e64[EE + e];
        }
    } else {
        for (int e = i; e < EE; e += stride) {
            g_src[e] = e32[e];
            g_dst[e] = e32[EE + e];
        }
    }
}

// ---------------- K0: zero agg_m, pos_out = pos ------------------------------
__global__ void init_kernel(const float* __restrict__ pos, float* __restrict__ out_pos)
{
    int i = blockIdx.x * blockDim.x + threadIdx.x;
    int stride = gridDim.x * blockDim.x;
    for (int j = i; j < NN * HID; j += stride) g_aggm[j] = 0.0f;
    for (int j = i; j < NN * 3;   j += stride) out_pos[j] = pos[j];
}

// ---------------- K1: A = x@Wa, B = x@Wb (tf32 MMA, 512 thr) ------------------
#define PB_SMEM (51712 * 4)
__global__ __launch_bounds__(512, 1)
void preab_kernel(const float* __restrict__ x, const float* __restrict__ e_w1)
{
    extern __shared__ float sm[];
    float* As  = sm;
    float* B1s = sm + 16896;
    float* B2s = sm + 34304;
    const uint32_t* Au  = (const uint32_t*)As;
    const uint32_t* B1u = (const uint32_t*)B1s;
    const uint32_t* B2u = (const uint32_t*)B2s;

    int tid = threadIdx.x, warp = tid >> 5, lane = tid & 31;
    int g = lane >> 2, t = lane & 3;
    int wm = warp >> 2, wn = warp & 3;
    int mbase = wm * 32, nbase = wn * 32;
    int n0 = blockIdx.x * 128;

    for (int idx = tid; idx < 16384; idx += 512) {
        int row = idx >> 7, k = idx & 127;
        float v = (n0 + row < NN) ? x[(size_t)(n0 + row) * 128 + k] : 0.f;
        As[row * ASTR + k]  = __uint_as_float(f2tf32(v));
        int kp = permn(k);
        B1s[row * BSTR + kp] = __uint_as_float(f2tf32(e_w1[row * 128 + k]));
        B2s[row * BSTR + kp] = __uint_as_float(f2tf32(e_w1[(128 + row) * 128 + k]));
    }
    __syncthreads();

    float c[2][4][4];
#pragma unroll
    for (int mt = 0; mt < 2; mt++)
#pragma unroll
        for (int nt = 0; nt < 4; nt++)
#pragma unroll
            for (int j = 0; j < 4; j++) c[mt][nt][j] = 0.f;
    warp_gemm2(Au, B1u, c, mbase, nbase, g, t);
#pragma unroll
    for (int mt = 0; mt < 2; mt++) {
        int r0 = mbase + mt * 16 + g, r1 = r0 + 8;
#pragma unroll
        for (int nt = 0; nt < 4; nt++) {
            int c0 = nbase + nt * 8 + 2 * t;
            if (n0 + r0 < NN)
                *(float2*)(g_A + (size_t)(n0 + r0) * 128 + c0) = make_float2(c[mt][nt][0], c[mt][nt][1]);
            if (n0 + r1 < NN)
                *(float2*)(g_A + (size_t)(n0 + r1) * 128 + c0) = make_float2(c[mt][nt][2], c[mt][nt][3]);
        }
    }

#pragma unroll
    for (int mt = 0; mt < 2; mt++)
#pragma unroll
        for (int nt = 0; nt < 4; nt++)
#pragma unroll
            for (int j = 0; j < 4; j++) c[mt][nt][j] = 0.f;
    warp_gemm2(Au, B2u, c, mbase, nbase, g, t);
#pragma unroll
    for (int mt = 0; mt < 2; mt++) {
        int r0 = mbase + mt * 16 + g, r1 = r0 + 8;
#pragma unroll
        for (int nt = 0; nt < 4; nt++) {
            int c0 = nbase + nt * 8 + 2 * t;
            if (n0 + r0 < NN)
                *(float2*)(g_B + (size_t)(n0 + r0) * 128 + c0) = make_float2(c[mt][nt][0], c[mt][nt][1]);
            if (n0 + r1 < NN)
                *(float2*)(g_B + (size_t)(n0 + r1) * 128 + c0) = make_float2(c[mt][nt][2], c[mt][nt][3]);
        }
    }
}

// ---------------- K2: persistent edge kernel ----------------------------------
// Two independent 512-thread groups; GEMM1 tf32 paired-A, GEMM2 bf16.
#define EO_A    0                       // 2 groups x 32 blocks x 264 = 16896 floats
#define EO_B1   16896                   // tf32, 128*BSTR = 17408
#define EO_B2   34304                   // bf16-packed, 64*B2STR = 8448
#define EO_SV   42752                   // shared constants (1408 floats)
#define EO_GRP  44160                   // per-group scratch, 1408 floats each
// shared const indices (relative to sv)
#define SV_WC0  0
#define SV_WC1  128
#define SV_WD   256
#define SV_B1   384
#define SV_I1   512    // interleaved (u1, vb1) pairs
#define SV_IG   768    // interleaved (g2, be2) pairs
#define SV_I2   1024   // interleaved (u2, vb2) pairs
#define SV_CW2  1280
// per-group indices (relative to gsv)
#define GV_RELX 0
#define GV_RELY 64
#define GV_RELZ 128
#define GV_R2   192
#define GV_EA0  256
#define GV_EA1  320
#define GV_MU1  384
#define GV_RS1  448
#define GV_SUM  512    // [64][4]
#define GV_SQ   768    // [64][4]
#define GV_SUM2 1024   // [64][4]
#define GV_IDX  1280   // ints: 64 dst, 64 src
#define GRP_FLOATS 1408
#define EDGE_SMEM ((EO_GRP + 2 * GRP_FLOATS) * 4)   // 187904 bytes

#define BARG(id) asm volatile("bar.sync %0, 512;" :: "r"(id) : "memory")

__global__ __launch_bounds__(1024, 1)
void edge_kernel(const float* __restrict__ pos,
                 const float* __restrict__ ea,
                 const float* __restrict__ e_w1, const float* __restrict__ e_b1,
                 const float* __restrict__ e_g1, const float* __restrict__ e_be1,
                 const float* __restrict__ e_w2, const float* __restrict__ e_b2,
                 const float* __restrict__ e_g2, const float* __restrict__ e_be2,
                 const float* __restrict__ c_w1, const float* __restrict__ c_b1,
                 const float* __restrict__ c_w2, const float* __restrict__ c_b2,
                 float* __restrict__ out_pos)
{
    extern __shared__ float sm[];
    float* B1s = sm + EO_B1;
    uint32_t* B2h = (uint32_t*)(sm + EO_B2);
    float* sv  = sm + EO_SV;
    const uint32_t* B1u = (const uint32_t*)B1s;

    int tid = threadIdx.x, warp = tid >> 5, lane = tid & 31;
    int gid = warp >> 4;
    int wig = warp & 15;
    int gtid = tid & 511;
    int bar = gid + 1;
    int g = lane >> 2, t = lane & 3;
    int wm = wig >> 2, wn = wig & 3;
    int mbase = wm * 16, nbase = wn * 32;

    float* As  = sm + EO_A + gid * (32 * APBLK);   // 8448 floats per group
    float* gsv = sm + EO_GRP + gid * GRP_FLOATS;
    int*   gdst = (int*)(gsv + GV_IDX);
    int*   gsrc = gdst + 64;
    const uint64_t* Ap = (const uint64_t*)As;
    uint32_t* Zu = (uint32_t*)As;          // bf16-packed z, aliases dead A region

    // ---- stage weights + shared constants ----
    for (int idx = tid; idx < 16384; idx += 1024) {
        int k = idx >> 7, n = idx & 127;
        B1s[k * BSTR + permn(n)] = __uint_as_float(f2tf32(e_g1[k] * e_w2[k * 128 + n]));
    }
    for (int idx = tid; idx < 8192; idx += 1024) {
        int kk = idx >> 7, n = idx & 127;
        float v0 = e_g2[2 * kk]     * c_w1[(2 * kk) * 128 + n];
        float v1 = e_g2[2 * kk + 1] * c_w1[(2 * kk + 1) * 128 + n];
        B2h[kk * B2STR + permn(n)] = packbf2(v0, v1);
    }
    if (tid < 128) {
        sv[SV_WC0 + tid] = e_w1[256 * 128 + tid];
        sv[SV_WC1 + tid] = e_w1[257 * 128 + tid];
        sv[SV_WD  + tid] = e_w1[258 * 128 + tid];
        sv[SV_B1  + tid] = e_b1[tid];
        sv[SV_IG  + 2 * tid]     = e_g2[tid];
        sv[SV_IG  + 2 * tid + 1] = e_be2[tid];
        sv[SV_CW2 + tid] = c_w2[tid];
    }
    if (tid < 512) {
        int quad = tid >> 7, n = tid & 127;
        float acc = 0.f;
        if (quad == 0) {
            for (int k = 0; k < 128; k++) acc += e_g1[k] * e_w2[k * 128 + n];
            sv[SV_I1 + 2 * n] = acc;
        } else if (quad == 1) {
            for (int k = 0; k < 128; k++) acc += e_be1[k] * e_w2[k * 128 + n];
            sv[SV_I1 + 2 * n + 1] = acc + e_b2[n];
        } else if (quad == 2) {
            for (int k = 0; k < 128; k++) acc += e_g2[k] * c_w1[k * 128 + n];
            sv[SV_I2 + 2 * n] = acc;
        } else {
            for (int k = 0; k < 128; k++) acc += e_be2[k] * c_w1[k * 128 + n];
            sv[SV_I2 + 2 * n + 1] = acc + c_b1[n];
        }
    }
    float cb2 = c_b2[0];
    __syncthreads();

    int k4 = lane * 4;
    bool first = true;

    const int ntiles = EE / 64;
    for (int tile = blockIdx.x * 2 + gid; tile < ntiles; tile += 2 * gridDim.x) {
        int e0 = tile * 64;
        // ---- phase A (gtid<64): prev-tile pos atomics + stage edge meta ----
        if (gtid < 64) {
            if (!first) {
                float coef = gsv[GV_SUM2 + gtid * 4] + gsv[GV_SUM2 + gtid * 4 + 1]
                           + gsv[GV_SUM2 + gtid * 4 + 2] + gsv[GV_SUM2 + gtid * 4 + 3] + cb2;
                int dip = gdst[gtid];
                atomicAdd(&out_pos[dip * 3 + 0], gsv[GV_RELX + gtid] * coef);
                atomicAdd(&out_pos[dip * 3 + 1], gsv[GV_RELY + gtid] * coef);
                atomicAdd(&out_pos[dip * 3 + 2], gsv[GV_RELZ + gtid] * coef);
            }
            int e = e0 + gtid;
            int si = g_src[e], di = g_dst[e];
            float rx = pos[di * 3 + 0] - pos[si * 3 + 0];
            float ry = pos[di * 3 + 1] - pos[si * 3 + 1];
            float rz = pos[di * 3 + 2] - pos[si * 3 + 2];
            gsrc[gtid] = si; gdst[gtid] = di;
            gsv[GV_RELX + gtid] = rx; gsv[GV_RELY + gtid] = ry; gsv[GV_RELZ + gtid] = rz;
            gsv[GV_R2 + gtid]  = rx * rx + ry * ry + rz * rz;
            gsv[GV_EA0 + gtid] = ea[2 * e];
            gsv[GV_EA1 + gtid] = ea[2 * e + 1];
        }
        first = false;
        BARG(bar);

        // ---- layer-1: gather + SiLU -> paired As (tf32); row stats ----
        {
            float4 wc0 = *(const float4*)(sv + SV_WC0 + k4);
            float4 wc1 = *(const float4*)(sv + SV_WC1 + k4);
            float4 wdv = *(const float4*)(sv + SV_WD  + k4);
            float4 b1v = *(const float4*)(sv + SV_B1  + k4);
#pragma unroll
            for (int pp = 0; pp < 2; pp++) {
                int pi = wig * 2 + pp;                       // 0..31
                int rowA = ((pi >> 3) << 4) + (pi & 7);
                int rowB = rowA + 8;
                int siA = gsrc[rowA], diA = gdst[rowA];
                int siB = gsrc[rowB], diB = gdst[rowB];
                float4 aA = *(const float4*)(g_A + (size_t)siA * 128 + k4);
                float4 bA = *(const float4*)(g_B + (size_t)diA * 128 + k4);
                float4 aB = *(const float4*)(g_A + (size_t)siB * 128 + k4);
                float4 bB = *(const float4*)(g_B + (size_t)diB * 128 + k4);
                float eA0 = gsv[GV_EA0 + rowA], eA1 = gsv[GV_EA1 + rowA], rA2 = gsv[GV_R2 + rowA];
                float eB0 = gsv[GV_EA0 + rowB], eB1 = gsv[GV_EA1 + rowB], rB2 = gsv[GV_R2 + rowB];
                float4 oA, oB;
                oA.x = silu_f(aA.x + bA.x + eA0 * wc0.x + eA1 * wc1.x + rA2 * wdv.x + b1v.x);
                oA.y = silu_f(aA.y + bA.y + eA0 * wc0.y + eA1 * wc1.y + rA2 * wdv.y + b1v.y);
                oA.z = silu_f(aA.z + bA.z + eA0 * wc0.z + eA1 * wc1.z + rA2 * wdv.z + b1v.z);
                oA.w = silu_f(aA.w + bA.w + eA0 * wc0.w + eA1 * wc1.w + rA2 * wdv.w + b1v.w);
                oB.x = silu_f(aB.x + bB.x + eB0 * wc0.x + eB1 * wc1.x + rB2 * wdv.x + b1v.x);
                oB.y = silu_f(aB.y + bB.y + eB0 * wc0.y + eB1 * wc1.y + rB2 * wdv.y + b1v.y);
                oB.z = silu_f(aB.z + bB.z + eB0 * wc0.z + eB1 * wc1.z + rB2 * wdv.z + b1v.z);
                oB.w = silu_f(aB.w + bB.w + eB0 * wc0.w + eB1 * wc1.w + rB2 * wdv.w + b1v.w);
                float sA = oA.x + oA.y + oA.z + oA.w;
                float qA = oA.x * oA.x + oA.y * oA.y + oA.z * oA.z + oA.w * oA.w;
                float sB = oB.x + oB.y + oB.z + oB.w;
                float qB = oB.x * oB.x + oB.y * oB.y + oB.z * oB.z + oB.w * oB.w;
#pragma unroll
                for (int off = 16; off > 0; off >>= 1) {
                    sA += __shfl_xor_sync(0xffffffffu, sA, off);
                    qA += __shfl_xor_sync(0xffffffffu, qA, off);
                    sB += __shfl_xor_sync(0xffffffffu, sB, off);
                    qB += __shfl_xor_sync(0xffffffffu, qB, off);
                }
                uint4 t0, t1;
                t0.x = f2tf32(oA.x); t0.y = f2tf32(oB.x);
                t0.z = f2tf32(oA.y); t0.w = f2tf32(oB.y);
                t1.x = f2tf32(oA.z); t1.y = f2tf32(oB.z);
                t1.z = f2tf32(oA.w); t1.w = f2tf32(oB.w);
                float* base = As + pi * APBLK + 8 * lane;
                *(uint4*)base = t0;
                *(uint4*)(base + 4) = t1;
                if (lane == 0) {
                    float muA = sA * (1.0f / 128.0f);
                    gsv[GV_MU1 + rowA] = muA;
                    gsv[GV_RS1 + rowA] = rsqrtf(qA * (1.0f / 128.0f) - muA * muA + EPSL);
                    float muB = sB * (1.0f / 128.0f);
                    gsv[GV_MU1 + rowB] = muB;
                    gsv[GV_RS1 + rowB] = rsqrtf(qB * (1.0f / 128.0f) - muB * muB + EPSL);
                }
            }
        }
        BARG(bar);

        // ---- GEMM1: h @ (g1 ∘ e_w2), tf32 paired-A ----
        float c[4][4];
#pragma unroll
        for (int nt = 0; nt < 4; nt++)
#pragma unroll
            for (int j = 0; j < 4; j++) c[nt][j] = 0.f;
        warp_gemm1p(Ap, B1u, c, wm, nbase, g, t);
        BARG(bar);

        // ---- ep1: y = rs1*(d - mu1*u1) + vb1 ; z = silu(y) -> Z (bf16) + partials ----
        {
            int r0 = mbase + g, r1 = r0 + 8;
            float rsA = gsv[GV_RS1 + r0], bA = rsA * gsv[GV_MU1 + r0];
            float rsB = gsv[GV_RS1 + r1], bB = rsB * gsv[GV_MU1 + r1];
            float s0 = 0.f, q0 = 0.f, s1 = 0.f, q1 = 0.f;
#pragma unroll
            for (int nt = 0; nt < 4; nt++) {
                int c0 = nbase + nt * 8 + 2 * t;
                float4 P = *(const float4*)(sv + SV_I1 + 2 * c0);   // u1a, vba, u1b, vbb
                float z0 = silu_f(rsA * c[nt][0] - bA * P.x + P.y);
                float z1 = silu_f(rsA * c[nt][1] - bA * P.z + P.w);
                float z2 = silu_f(rsB * c[nt][2] - bB * P.x + P.y);
                float z3 = silu_f(rsB * c[nt][3] - bB * P.z + P.w);
                c[nt][0] = z0; c[nt][1] = z1; c[nt][2] = z2; c[nt][3] = z3;
                Zu[r0 * ZSTR + (c0 >> 1)] = packbf2(z0, z1);
                Zu[r1 * ZSTR + (c0 >> 1)] = packbf2(z2, z3);
                s0 += z0 + z1; q0 += z0 * z0 + z1 * z1;
                s1 += z2 + z3; q1 += z2 * z2 + z3 * z3;
            }
#pragma unroll
            for (int off = 1; off <= 2; off <<= 1) {
                s0 += __shfl_xor_sync(0xffffffffu, s0, off);
                s1 += __shfl_xor_sync(0xffffffffu, s1, off);
                q0 += __shfl_xor_sync(0xffffffffu, q0, off);
                q1 += __shfl_xor_sync(0xffffffffu, q1, off);
            }
            if (t == 0) {
                gsv[GV_SUM + r0 * 4 + wn] = s0;
                gsv[GV_SQ  + r0 * 4 + wn] = q0;
                gsv[GV_SUM + r1 * 4 + wn] = s1;
                gsv[GV_SQ  + r1 * 4 + wn] = q1;
            }
        }
        BARG(bar);

        // ---- phase B: local LN2 stats, aggm atomics, GEMM2 (bf16), ep2 ----
        {
            int r0 = mbase + g, r1 = r0 + 8;
            float s0 = gsv[GV_SUM + r0 * 4] + gsv[GV_SUM + r0 * 4 + 1]
                     + gsv[GV_SUM + r0 * 4 + 2] + gsv[GV_SUM + r0 * 4 + 3];
            float q0 = gsv[GV_SQ + r0 * 4] + gsv[GV_SQ + r0 * 4 + 1]
                     + gsv[GV_SQ + r0 * 4 + 2] + gsv[GV_SQ + r0 * 4 + 3];
            float s1 = gsv[GV_SUM + r1 * 4] + gsv[GV_SUM + r1 * 4 + 1]
                     + gsv[GV_SUM + r1 * 4 + 2] + gsv[GV_SUM + r1 * 4 + 3];
            float q1 = gsv[GV_SQ + r1 * 4] + gsv[GV_SQ + r1 * 4 + 1]
                     + gsv[GV_SQ + r1 * 4 + 2] + gsv[GV_SQ + r1 * 4 + 3];
            float mu0 = s0 * (1.0f / 128.0f);
            float rs0 = rsqrtf(q0 * (1.0f / 128.0f) - mu0 * mu0 + EPSL);
            float mu1 = s1 * (1.0f / 128.0f);
            float rs1 = rsqrtf(q1 * (1.0f / 128.0f) - mu1 * mu1 + EPSL);

            int d0 = gdst[r0], d1 = gdst[r1];
#pragma unroll
            for (int nt = 0; nt < 4; nt++) {
                int c0 = nbase + nt * 8 + 2 * t;
                float4 G = *(const float4*)(sv + SV_IG + 2 * c0);   // g2a, bea, g2b, beb
                float m0 = (c[nt][0] - mu0) * rs0 * G.x + G.y;
                float m1 = (c[nt][1] - mu0) * rs0 * G.z + G.w;
                float m2 = (c[nt][2] - mu1) * rs1 * G.x + G.y;
                float m3 = (c[nt][3] - mu1) * rs1 * G.z + G.w;
                asm volatile("red.global.add.v2.f32 [%0], {%1, %2};"
                             :: "l"(g_aggm + (size_t)d0 * 128 + c0), "f"(m0), "f"(m1) : "memory");
                asm volatile("red.global.add.v2.f32 [%0], {%1, %2};"
                             :: "l"(g_aggm + (size_t)d1 * 128 + c0), "f"(m2), "f"(m3) : "memory");
            }

            // GEMM2: z @ (g2 ∘ c_w1), bf16 m16n8k16
#pragma unroll
            for (int nt = 0; nt < 4; nt++)
#pragma unroll
                for (int j = 0; j < 4; j++) c[nt][j] = 0.f;
            warp_gemm_bf(Zu, B2h, c, mbase, nbase, g, t);

            // ep2: val = rs*(d - mu*u2) + vb2 ; coef partials -> SUM2
            float b0 = rs0 * mu0, b1 = rs1 * mu1;
            float p0 = 0.f, p1 = 0.f;
#pragma unroll
            for (int nt = 0; nt < 4; nt++) {
                int c0 = nbase + nt * 8 + 2 * t;
                float4 Q = *(const float4*)(sv + SV_I2 + 2 * c0);   // u2a, vba, u2b, vbb
                float2 W = *(const float2*)(sv + SV_CW2 + c0);
                p0 += silu_f(rs0 * c[nt][0] - b0 * Q.x + Q.y) * W.x
                    + silu_f(rs0 * c[nt][1] - b0 * Q.z + Q.w) * W.y;
                p1 += silu_f(rs1 * c[nt][2] - b1 * Q.x + Q.y) * W.x
                    + silu_f(rs1 * c[nt][3] - b1 * Q.z + Q.w) * W.y;
            }
#pragma unroll
            for (int off = 1; off <= 2; off <<= 1) {
                p0 += __shfl_xor_sync(0xffffffffu, p0, off);
                p1 += __shfl_xor_sync(0xffffffffu, p1, off);
            }
            if (t == 0) {
                gsv[GV_SUM2 + r0 * 4 + wn] = p0;
                gsv[GV_SUM2 + r1 * 4 + wn] = p1;
            }
        }
        BARG(bar);
    }

    // ---- final tile's pos atomics (per group) ----
    if (!first && gtid < 64) {
        float coef = gsv[GV_SUM2 + gtid * 4] + gsv[GV_SUM2 + gtid * 4 + 1]
                   + gsv[GV_SUM2 + gtid * 4 + 2] + gsv[GV_SUM2 + gtid * 4 + 3] + cb2;
        int di = gdst[gtid];
        atomicAdd(&out_pos[di * 3 + 0], gsv[GV_RELX + gtid] * coef);
        atomicAdd(&out_pos[di * 3 + 1], gsv[GV_RELY + gtid] * coef);
        atomicAdd(&out_pos[di * 3 + 2], gsv[GV_RELZ + gtid] * coef);
    }
}

// ---------------- K3: node MLP + residual (tf32 MMA, 512 thr) ----------------
#define NV_B1   0
#define NV_I    128    // interleaved (u, vb) pairs
#define NV_MU   384
#define NV_RS   512
#define NV_SUM  640    // [128][4]
#define NV_SQ   1152   // [128][4]
#define NV_FLOATS 1664
#define ND_SMEM ((34304 + NV_FLOATS) * 4)
__global__ __launch_bounds__(512, 1)
void node_kernel(const float* __restrict__ x,
                 const float* __restrict__ n_w1, const float* __restrict__ n_b1,
                 const float* __restrict__ n_g1, const float* __restrict__ n_be1,
                 const float* __restrict__ n_w2, const float* __restrict__ n_b2,
                 float* __restrict__ out_x)
{
    extern __shared__ float sm[];
    float* As = sm;
    float* Bs = sm + 16896;
    float* sv = sm + 34304;
    const uint32_t* Au = (const uint32_t*)As;
    const uint32_t* Bu = (const uint32_t*)Bs;

    int tid = threadIdx.x, warp = tid >> 5, lane = tid & 31;
    int g = lane >> 2, t = lane & 3;
    int wm = warp >> 2, wn = warp & 3;
    int mbase = wm * 32, nbase = wn * 32;
    int n0 = blockIdx.x * 128;

    if (tid < 128) sv[NV_B1 + tid] = n_b1[tid];
    if (tid >= 128 && tid < 384) {
        int half = (tid - 128) >> 7, n = tid & 127;
        float acc = 0.f;
        if (half == 0) {
            for (int k = 0; k < 128; k++) acc += n_g1[k] * n_w2[k * 128 + n];
            sv[NV_I + 2 * n] = acc;
        } else {
            for (int k = 0; k < 128; k++) acc += n_be1[k] * n_w2[k * 128 + n];
            sv[NV_I + 2 * n + 1] = acc + n_b2[n];
        }
    }

    // phase 1: x @ W1a
    for (int idx = tid; idx < 16384; idx += 512) {
        int row = idx >> 7, k = idx & 127;
        float v = (n0 + row < NN) ? x[(size_t)(n0 + row) * 128 + k] : 0.f;
        As[row * ASTR + k] = __uint_as_float(f2tf32(v));
        Bs[row * BSTR + permn(k)] = __uint_as_float(f2tf32(n_w1[row * 128 + k]));
    }
    __syncthreads();

    float c[2][4][4];
#pragma unroll
    for (int mt = 0; mt < 2; mt++)
#pragma unroll
        for (int nt = 0; nt < 4; nt++)
#pragma unroll
            for (int j = 0; j < 4; j++) c[mt][nt][j] = 0.f;
    warp_gemm2(Au, Bu, c, mbase, nbase, g, t);
    __syncthreads();

    // phase 2: + aggm @ W1b
    for (int idx = tid; idx < 16384; idx += 512) {
        int row = idx >> 7, k = idx & 127;
        float v = (n0 + row < NN) ? g_aggm[(size_t)(n0 + row) * 128 + k] : 0.f;
        As[row * ASTR + k] = __uint_as_float(f2tf32(v));
        Bs[row * BSTR + permn(k)] = __uint_as_float(f2tf32(n_w1[(128 + row) * 128 + k]));
    }
    __syncthreads();
    warp_gemm2(Au, Bu, c, mbase, nbase, g, t);
    __syncthreads();

    // ep1: z = silu(acc + b1) -> As (tf32) + row stats
#pragma unroll
    for (int mt = 0; mt < 2; mt++) {
        int r0 = mbase + mt * 16 + g, r1 = r0 + 8;
        float s0 = 0.f, q0 = 0.f, s1 = 0.f, q1 = 0.f;
#pragma unroll
        for (int nt = 0; nt < 4; nt++) {
            int c0 = nbase + nt * 8 + 2 * t;
            float ba = sv[NV_B1 + c0], bb = sv[NV_B1 + c0 + 1];
            float z0 = silu_f(c[mt][nt][0] + ba);
            float z1 = silu_f(c[mt][nt][1] + bb);
            float z2 = silu_f(c[mt][nt][2] + ba);
            float z3 = silu_f(c[mt][nt][3] + bb);
            uint2 p0; p0.x = f2tf32(z0); p0.y = f2tf32(z1);
            uint2 p1; p1.x = f2tf32(z2); p1.y = f2tf32(z3);
            *(uint2*)(As + r0 * ASTR + c0) = p0;
            *(uint2*)(As + r1 * ASTR + c0) = p1;
            s0 += z0 + z1; q0 += z0 * z0 + z1 * z1;
            s1 += z2 + z3; q1 += z2 * z2 + z3 * z3;
        }
#pragma unroll
        for (int off = 1; off <= 2; off <<= 1) {
            s0 += __shfl_xor_sync(0xffffffffu, s0, off);
            s1 += __shfl_xor_sync(0xffffffffu, s1, off);
            q0 += __shfl_xor_sync(0xffffffffu, q0, off);
            q1 += __shfl_xor_sync(0xffffffffu, q1, off);
        }
        if (t == 0) {
            sv[NV_SUM + r0 * 4 + wn] = s0;
            sv[NV_SQ  + r0 * 4 + wn] = q0;
            sv[NV_SUM + r1 * 4 + wn] = s1;
            sv[NV_SQ  + r1 * 4 + wn] = q1;
        }
    }
    __syncthreads();
    if (tid < 128) {
        float s = sv[NV_SUM + tid * 4] + sv[NV_SUM + tid * 4 + 1]
                + sv[NV_SUM + tid * 4 + 2] + sv[NV_SUM + tid * 4 + 3];
        float q = sv[NV_SQ + tid * 4] + sv[NV_SQ + tid * 4 + 1]
                + sv[NV_SQ + tid * 4 + 2] + sv[NV_SQ + tid * 4 + 3];
        float mu = s * (1.0f / 128.0f);
        sv[NV_MU + tid] = mu;
        sv[NV_RS + tid] = rsqrtf(q * (1.0f / 128.0f) - mu * mu + EPSL);
    }
    // stage (g1 ∘ W2) into Bs (n-permuted)
    for (int idx = tid; idx < 16384; idx += 512) {
        int k = idx >> 7, n = idx & 127;
        Bs[k * BSTR + permn(n)] = __uint_as_float(f2tf32(n_g1[k] * n_w2[k * 128 + n]));
    }
    __syncthreads();

    // GEMM2: z @ (g1 ∘ W2)
#pragma unroll
    for (int mt = 0; mt < 2; mt++)
#pragma unroll
        for (int nt = 0; nt < 4; nt++)
#pragma unroll
            for (int j = 0; j < 4; j++) c[mt][nt][j] = 0.f;
    warp_gemm2(Au, Bu, c, mbase, nbase, g, t);

    // ep2: out = x + rs*d - rs*mu*u + vb
#pragma unroll
    for (int mt = 0; mt < 2; mt++) {
        int r0 = mbase + mt * 16 + g, r1 = r0 + 8;
        float rs0 = sv[NV_RS + r0], b0 = rs0 * sv[NV_MU + r0];
        float rs1 = sv[NV_RS + r1], b1 = rs1 * sv[NV_MU + r1];
#pragma unroll
        for (int nt = 0; nt < 4; nt++) {
            int c0 = nbase + nt * 8 + 2 * t;
            float4 Q = *(const float4*)(sv + NV_I + 2 * c0);   // ua, va, ub, vb
            if (n0 + r0 < NN) {
                float2 xv = *(const float2*)(x + (size_t)(n0 + r0) * 128 + c0);
                *(float2*)(out_x + (size_t)(n0 + r0) * 128 + c0) =
                    make_float2(xv.x + rs0 * c[mt][nt][0] - b0 * Q.x + Q.y,
                                xv.y + rs0 * c[mt][nt][1] - b0 * Q.z + Q.w);
            }
            if (n0 + r1 < NN) {
                float2 xv = *(const float2*)(x + (size_t)(n0 + r1) * 128 + c0);
                *(float2*)(out_x + (size_t)(n0 + r1) * 128 + c0) =
                    make_float2(xv.x + rs1 * c[mt][nt][2] - b1 * Q.x + Q.y,
                                xv.y + rs1 * c[mt][nt][3] - b1 * Q.z + Q.w);
            }
        }
    }
}

// ---------------- launch ------------------------------------------------------
extern "C" void kernel_launch(void* const* d_in, const int* in_sizes, int n_in,
                              void* d_out, int out_size)
{
    const float*     x     = (const float*)d_in[0];
    const float*     pos   = (const float*)d_in[1];
    const void*      ei    = d_in[2];
    const float*     ea    = (const float*)d_in[3];
    const float*     e_w1  = (const float*)d_in[4];
    const float*     e_b1  = (const float*)d_in[5];
    const float*     e_g1  = (const float*)d_in[6];
    const float*     e_be1 = (const float*)d_in[7];
    const float*     e_w2  = (const float*)d_in[8];
    const float*     e_b2  = (const float*)d_in[9];
    const float*     e_g2  = (const float*)d_in[10];
    const float*     e_be2 = (const float*)d_in[11];
    const float*     n_w1  = (const float*)d_in[12];
    const float*     n_b1  = (const float*)d_in[13];
    const float*     n_g1  = (const float*)d_in[14];
    const float*     n_be1 = (const float*)d_in[15];
    const float*     n_w2  = (const float*)d_in[16];
    const float*     n_b2  = (const float*)d_in[17];
    const float*     c_w1  = (const float*)d_in[18];
    const float*     c_b1  = (const float*)d_in[19];
    const float*     c_w2  = (const float*)d_in[20];
    const float*     c_b2  = (const float*)d_in[21];

    float* out_x   = (float*)d_out;
    float* out_pos = (float*)d_out + (size_t)NN * FEAT;

    cudaFuncSetAttribute(preab_kernel, cudaFuncAttributeMaxDynamicSharedMemorySize, PB_SMEM);
    cudaFuncSetAttribute(edge_kernel,  cudaFuncAttributeMaxDynamicSharedMemorySize, EDGE_SMEM);
    cudaFuncSetAttribute(node_kernel,  cudaFuncAttributeMaxDynamicSharedMemorySize, ND_SMEM);

    conv_idx_kernel<<<256, 256>>>(ei);
    init_kernel<<<256, 256>>>(pos, out_pos);
    preab_kernel<<<(NN + 127) / 128, 512, PB_SMEM>>>(x, e_w1);
    edge_kernel<<<148, 1024, EDGE_SMEM>>>(pos, ea,
                                          e_w1, e_b1, e_g1, e_be1,
                                          e_w2, e_b2, e_g2, e_be2,
                                          c_w1, c_b1, c_w2, c_b2,
                                          out_pos);
    node_kernel<<<(NN + 127) / 128, 512, ND_SMEM>>>(x, n_w1, n_b1, n_g1, n_be1,
                                                    n_w2, n_b2, out_x);
}